// round 13
// baseline (speedup 1.0000x reference)
#include <cuda_runtime.h>
#include <math.h>

typedef unsigned long long u64;

// Packed fp32x2 helpers (SASS FFMA2 path — only reachable via PTX)
__device__ __forceinline__ u64 pk(float lo, float hi) {
    u64 r; asm("mov.b64 %0, {%1, %2};" : "=l"(r) : "f"(lo), "f"(hi)); return r;
}
__device__ __forceinline__ float2 upk(u64 v) {
    float2 r; asm("mov.b64 {%0, %1}, %2;" : "=f"(r.x), "=f"(r.y) : "l"(v)); return r;
}
__device__ __forceinline__ u64 fma2(u64 a, u64 b, u64 c) {
    u64 d; asm("fma.rn.f32x2 %0, %1, %2, %3;" : "=l"(d) : "l"(a), "l"(b), "l"(c)); return d;
}
__device__ __forceinline__ u64 add2(u64 a, u64 b) {
    u64 d; asm("add.rn.f32x2 %0, %1, %2;" : "=l"(d) : "l"(a), "l"(b)); return d;
}

// Problem dims
#define VOL 18874368       // 4*64*8*96*96

// Scratch (device globals: the sanctioned no-alloc workaround)
__device__ float g_xc[VOL];      // conv0 output (pre-BN)
__device__ float g_q[VOL];       // [t][c][n]
__device__ float g_k[VOL];
__device__ float g_v[VOL];
__device__ float g_s[VOL];       // x + attn_out (pre-BN1)
__device__ float g_part[2 * 64 * 72];
__device__ float g_bn0[128];     // a[64], shift[64]
__device__ float g_bn1[128];
__device__ float g_m[2048];      // [b][c][t]
__device__ float g_w5[800];      // [b][t][25]

__device__ __forceinline__ float leaky(float v) { return v >= 0.f ? v : 0.01f * v; }

// ---------------------------------------------------------------------------
// K1: conv0 (3x3, pad 1, 64->64) -> g_xc, with packed f32x2 FMAs.
// Block: one (b,t,x) row. 256 thr = 64 c_out x 4 y-groups of 24 (12 pairs).
// Input rows stored TWICE in smem (aligned + shifted copy) so both pair
// parities are direct LDS.64 loads — no pack MOVs in the inner loop.
// ---------------------------------------------------------------------------
__global__ __launch_bounds__(256) void k_conv0(const float* __restrict__ h,
                                               const float* __restrict__ w,
                                               const float* __restrict__ bias) {
    __shared__ __align__(16) float se[3][104];   // se[r][j] = v(j)
    __shared__ __align__(16) float so[3][104];   // so[r][j] = v(j+1)
    __shared__ float w_s[576];
    int bt = blockIdx.y;
    int b = bt >> 3, t = bt & 7;
    int x = blockIdx.x;
    int co = threadIdx.x & 63;
    int yg = threadIdx.x >> 6;
    int ybase = yg * 24;

    u64 acc[12];
#pragma unroll
    for (int i = 0; i < 12; i++) acc[i] = 0ULL;

    const float* hp = h + ((long)(b * 64) * 8 + t) * 9216;  // + ci*73728

    for (int ci = 0; ci < 64; ci++) {
        __syncthreads();
        for (int i = threadIdx.x; i < 294; i += 256) {
            int r = i / 98, yy = i - r * 98;
            int gx = x + r - 1, gy = yy - 1;
            float v = 0.f;
            if ((unsigned)gx < 96u && (unsigned)gy < 96u)
                v = hp[ci * 73728 + gx * 96 + gy];
            se[r][yy] = v;
            if (yy) so[r][yy - 1] = v;
        }
        for (int i = threadIdx.x; i < 576; i += 256) {
            int o = i / 9, k = i - o * 9;
            w_s[i] = w[(o * 64 + ci) * 9 + k];
        }
        __syncthreads();

        float wr[9];
#pragma unroll
        for (int k = 0; k < 9; k++) wr[k] = w_s[co * 9 + k];

#pragma unroll
        for (int r = 0; r < 3; r++) {
            u64 W0 = pk(wr[r * 3], wr[r * 3]);
            u64 W1 = pk(wr[r * 3 + 1], wr[r * 3 + 1]);
            u64 W2 = pk(wr[r * 3 + 2], wr[r * 3 + 2]);
            const u64* pe = (const u64*)&se[r][ybase];
            const u64* po = (const u64*)&so[r][ybase];
#pragma unroll
            for (int j = 0; j < 12; j++) {
                acc[j] = fma2(pe[j],     W0, acc[j]);
                acc[j] = fma2(po[j],     W1, acc[j]);
                acc[j] = fma2(pe[j + 1], W2, acc[j]);
            }
        }
    }
    float bb = bias[co];
    float* op = g_xc + ((b * 64 + co) * 8 + t) * 9216 + x * 96 + ybase;
#pragma unroll
    for (int j = 0; j < 12; j++) {
        float2 v = upk(acc[j]);
        float2 r2; r2.x = v.x + bb; r2.y = v.y + bb;
        *(float2*)&op[2 * j] = r2;
    }
}

// ---------------------------------------------------------------------------
// K2: per-channel sum / sumsq partials (deterministic two-stage reduction)
// ---------------------------------------------------------------------------
__global__ __launch_bounds__(256) void k_stats(int which) {
    const float* src = which ? g_s : g_xc;
    int c = blockIdx.x;
    int chunk = blockIdx.y;
    float s = 0.f, q = 0.f;
    for (int i = threadIdx.x; i < 4096; i += 256) {
        int j = chunk * 4096 + i;
        int b = j / 73728;
        int r = j - b * 73728;
        float v = src[(b * 64 + c) * 73728 + r];
        s += v; q += v * v;
    }
    __shared__ float rs[256], rq[256];
    rs[threadIdx.x] = s; rq[threadIdx.x] = q;
    __syncthreads();
    for (int st = 128; st > 0; st >>= 1) {
        if (threadIdx.x < st) { rs[threadIdx.x] += rs[threadIdx.x + st];
                                rq[threadIdx.x] += rq[threadIdx.x + st]; }
        __syncthreads();
    }
    if (threadIdx.x == 0) {
        g_part[c * 72 + chunk] = rs[0];
        g_part[4608 + c * 72 + chunk] = rq[0];
    }
}

__global__ void k_finalize(int which, const float* __restrict__ gamma,
                           const float* __restrict__ beta) {
    int c = threadIdx.x;  // 64 threads
    float s = 0.f, q = 0.f;
    for (int i = 0; i < 72; i++) { s += g_part[c * 72 + i]; q += g_part[4608 + c * 72 + i]; }
    float mean = s * (1.f / 294912.f);
    float var = q * (1.f / 294912.f) - mean * mean;
    float a = gamma[c] * rsqrtf(var + 1e-5f);
    float* dst = which ? g_bn1 : g_bn0;
    dst[c] = a;
    dst[64 + c] = beta[c] - mean * a;
}

// ---------------------------------------------------------------------------
// K3: QKV projection with f32x2. Per (b,t): Out[192][9216] = W[192][64] @ x.
// Block = 256 positions. Activations stored DUPLICATED in smem ((x,x) pairs
// via one STS.64) so broadcast operands are direct LDS.64. Outputs paired
// (weight pairs free from row-major w tile). Thread: 8 outs x 8 positions
// (positions interleaved stride-32 -> conflict-free LDS.64, coalesced STG).
// ---------------------------------------------------------------------------
__global__ __launch_bounds__(256) void k_qkv(const float* __restrict__ W,
                                             const float* __restrict__ Wb) {
    extern __shared__ __align__(16) float sm[];
    float* in_d = sm;                 // 64 * 512 floats (duplicated pairs)
    float* w_s  = sm + 32768;         // 64 * 196 (transposed, padded)
    int bt = blockIdx.y;
    int b = bt >> 3, t = bt & 7;
    int s0 = blockIdx.x * 256;

    for (int i = threadIdx.x; i < 12288; i += 256) {
        int o = i >> 6, c = i & 63;
        w_s[c * 196 + o] = W[i];
    }
    for (int i = threadIdx.x; i < 4096; i += 256) {
        int c = i >> 6, g = (i & 63) * 4;
        float4 v4 = *(const float4*)&g_xc[((b * 64 + c) * 8 + t) * 9216 + s0 + g];
        float a = g_bn0[c], sh = g_bn0[64 + c];
        float e0 = leaky(a * v4.x + sh);
        float e1 = leaky(a * v4.y + sh);
        float e2 = leaky(a * v4.z + sh);
        float e3 = leaky(a * v4.w + sh);
        u64* dst = (u64*)(in_d + c * 512 + 2 * g);
        dst[0] = pk(e0, e0); dst[1] = pk(e1, e1);
        dst[2] = pk(e2, e2); dst[3] = pk(e3, e3);
    }
    __syncthreads();

    int pg = threadIdx.x & 31;
    int og = threadIdx.x >> 5;

    for (int p = 0; p < 3; p++) {
        u64 acc[4][8];
#pragma unroll
        for (int i = 0; i < 4; i++)
#pragma unroll
            for (int k = 0; k < 8; k++) acc[i][k] = 0ULL;

        for (int c = 0; c < 64; c++) {
            const u64* xrow = (const u64*)(in_d + c * 512);
            u64 xv[8];
#pragma unroll
            for (int k = 0; k < 8; k++) xv[k] = xrow[pg + 32 * k];
            const u64* wp = (const u64*)&w_s[c * 196 + p * 64 + og * 8];
            u64 w01 = wp[0], w23 = wp[1], w45 = wp[2], w67 = wp[3];
#pragma unroll
            for (int k = 0; k < 8; k++) {
                acc[0][k] = fma2(w01, xv[k], acc[0][k]);
                acc[1][k] = fma2(w23, xv[k], acc[1][k]);
                acc[2][k] = fma2(w45, xv[k], acc[2][k]);
                acc[3][k] = fma2(w67, xv[k], acc[3][k]);
            }
        }
        float* dst = (p == 0) ? g_q : (p == 1 ? g_k : g_v);
        float scale = (p == 0) ? 0.35355339059327373f : 1.f;
#pragma unroll
        for (int i = 0; i < 4; i++) {
            int o0 = og * 8 + 2 * i;
            float b0 = Wb[p * 64 + o0], b1 = Wb[p * 64 + o0 + 1];
            long base0 = (long)(t * 64 + o0) * 36864 + b * 9216 + s0 + pg;
            long base1 = base0 + 36864;
#pragma unroll
            for (int k = 0; k < 8; k++) {
                float2 v = upk(acc[i][k]);
                dst[base0 + 32 * k] = (v.x + b0) * scale;
                dst[base1 + 32 * k] = (v.y + b1) * scale;
            }
        }
    }
}

// ---------------------------------------------------------------------------
// K4: attention core + out-proj (f32x2) + residual -> g_s
// ---------------------------------------------------------------------------
__global__ __launch_bounds__(256) void k_attn(const float* __restrict__ Wo,
                                              const float* __restrict__ bo) {
    extern __shared__ __align__(16) float sm[];
    float* q_s  = sm;              // 512*17 = 8704
    float* k_s  = sm + 8704;
    float* v_s  = sm + 17408;
    float* o_s  = sm + 26112;      // 16*516 = 8256
    float* wo_s = sm + 34368;      // 4096
    float* ab_s = sm + 38464;      // 128
    float* bo_s = sm + 38592;      // 64

    int n0 = blockIdx.x * 16;
    int b = n0 / 9216;
    int s0 = n0 - b * 9216;

    for (int i = threadIdx.x; i < 8192; i += 256) {
        int tc = i >> 4, nl = i & 15;
        int ga = tc * 36864 + n0 + nl;
        q_s[tc * 17 + nl] = g_q[ga];
        k_s[tc * 17 + nl] = g_k[ga];
        v_s[tc * 17 + nl] = g_v[ga];
    }
    for (int i = threadIdx.x; i < 4096; i += 256) wo_s[i] = Wo[i];
    if (threadIdx.x < 128) ab_s[threadIdx.x] = g_bn0[threadIdx.x];
    else if (threadIdx.x < 192) bo_s[threadIdx.x - 128] = bo[threadIdx.x - 128];
    __syncthreads();

    // Phase B: per-(token, head) attention over T=8
    {
        int u = threadIdx.x >> 7;
        int rem = threadIdx.x & 127;
        int nl = rem & 15;
        int hh = rem >> 4;
#pragma unroll
        for (int qi = 0; qi < 4; qi++) {
            int qt = u * 4 + qi;
            float qr[8];
#pragma unroll
            for (int d = 0; d < 8; d++) qr[d] = q_s[(qt * 64 + hh * 8 + d) * 17 + nl];
            float sc[8];
#pragma unroll
            for (int kt = 0; kt < 8; kt++) {
                float s = 0.f;
#pragma unroll
                for (int d = 0; d < 8; d++)
                    s = fmaf(qr[d], k_s[(kt * 64 + hh * 8 + d) * 17 + nl], s);
                sc[kt] = s;
            }
            float mx = sc[0];
#pragma unroll
            for (int kt = 1; kt < 8; kt++) mx = fmaxf(mx, sc[kt]);
            float sum = 0.f;
#pragma unroll
            for (int kt = 0; kt < 8; kt++) { sc[kt] = __expf(sc[kt] - mx); sum += sc[kt]; }
            float inv = 1.f / sum;
#pragma unroll
            for (int d = 0; d < 8; d++) {
                float o = 0.f;
#pragma unroll
                for (int kt = 0; kt < 8; kt++)
                    o = fmaf(sc[kt], v_s[(kt * 64 + hh * 8 + d) * 17 + nl], o);
                o_s[nl * 516 + qt * 64 + hh * 8 + d] = o * inv;
            }
        }
    }
    __syncthreads();

    // Phase C: out-proj (packed pairs over c) + residual -> g_s
    {
        int nl = threadIdx.x & 15;
        int t  = (threadIdx.x >> 4) & 7;
        int half = threadIdx.x >> 7;
        u64 orow[32];
        const ulonglong2* op2 = (const ulonglong2*)&o_s[nl * 516 + t * 64];
#pragma unroll
        for (int i = 0; i < 16; i++) {
            ulonglong2 q2 = op2[i];
            orow[2 * i] = q2.x; orow[2 * i + 1] = q2.y;
        }
#pragma unroll 4
        for (int cc = 0; cc < 32; cc++) {
            int co = half * 32 + cc;
            const ulonglong2* wp2 = (const ulonglong2*)&wo_s[co * 64];
            u64 a0 = 0ULL, a1 = 0ULL;
#pragma unroll
            for (int i = 0; i < 16; i++) {
                ulonglong2 wv = wp2[i];
                a0 = fma2(orow[2 * i],     wv.x, a0);
                a1 = fma2(orow[2 * i + 1], wv.y, a1);
            }
            float2 s2 = upk(add2(a0, a1));
            float acc = s2.x + s2.y + bo_s[co];
            int ga = ((b * 64 + co) * 8 + t) * 9216 + s0 + nl;
            float x = leaky(ab_s[co] * g_xc[ga] + ab_s[64 + co]);
            g_s[ga] = x + acc;
        }
    }
}

// ---------------------------------------------------------------------------
// K6: m[b,c,t] = spatial mean of leaky(bn1(g_s))
// ---------------------------------------------------------------------------
__global__ __launch_bounds__(256) void k_mred() {
    int bct = blockIdx.x;
    int c = (bct >> 3) & 63;
    float a = g_bn1[c], sh = g_bn1[64 + c];
    const float* p = g_s + bct * 9216;
    float s = 0.f;
    for (int i = threadIdx.x; i < 9216; i += 256) s += leaky(a * p[i] + sh);
    __shared__ float rs[256];
    rs[threadIdx.x] = s;
    __syncthreads();
    for (int st = 128; st > 0; st >>= 1) {
        if (threadIdx.x < st) rs[threadIdx.x] += rs[threadIdx.x + st];
        __syncthreads();
    }
    if (threadIdx.x == 0) g_m[bct] = rs[0] * (1.f / 9216.f);
}

// ---------------------------------------------------------------------------
// K7: per-(b,t) 5x5 kernels
// ---------------------------------------------------------------------------
__global__ void k_kern(const float* __restrict__ w1, const float* __restrict__ b1) {
    for (int i = threadIdx.x; i < 800; i += 256) {
        int b = i / 200;
        int rem = i - b * 200;
        int o = rem / 8;
        int t = rem - o * 8;
        float s = b1[o];
        for (int c = 0; c < 64; c++)
            s = fmaf(w1[o * 64 + c], g_m[(b * 64 + c) * 8 + t], s);
        g_w5[(b * 8 + t) * 25 + o] = s;
    }
}

// ---------------------------------------------------------------------------
// K8: dynamic depthwise 5x5 conv with f32x2 y-pairs (dual-copy smem rows)
// 384 thr: 8 x-rows x 48 y-pairs, one pair per thread.
// ---------------------------------------------------------------------------
__global__ __launch_bounds__(384) void k_dyn(const float* __restrict__ h,
                                             float* __restrict__ out) {
    __shared__ __align__(16) float se[12][104];
    __shared__ __align__(16) float so[12][104];
    __shared__ float w_s[25];
    int plane = blockIdx.y;          // (b*64+c)*8+t
    int b = plane >> 9;
    int t = plane & 7;
    int bt = b * 8 + t;
    int x0 = blockIdx.x * 8;

    if (threadIdx.x < 25) w_s[threadIdx.x] = g_w5[bt * 25 + threadIdx.x];
    for (int i = threadIdx.x; i < 1200; i += 384) {
        int r = i / 100, c = i - r * 100;
        int gx = x0 + r - 2, gy = c - 2;
        float v = 0.f;
        if ((unsigned)gx < 96u && (unsigned)gy < 96u)
            v = h[plane * 9216 + gx * 96 + gy];
        se[r][c] = v;
        if (c) so[r][c - 1] = v;
    }
    __syncthreads();

    int xr = threadIdx.x / 48;
    int y = (threadIdx.x - xr * 48) * 2;
    u64 wpk[25];
#pragma unroll
    for (int i = 0; i < 25; i++) { float wv = w_s[i]; wpk[i] = pk(wv, wv); }

    u64 a0 = 0ULL, a1 = 0ULL;
#pragma unroll
    for (int di = 0; di < 5; di++) {
        const float* er  = se[xr + di];
        const float* orr = so[xr + di];
        a0 = fma2(*(const u64*)&er[y],       wpk[di * 5 + 0], a0);
        a1 = fma2(*(const u64*)&orr[y],      wpk[di * 5 + 1], a1);
        a0 = fma2(*(const u64*)&er[y + 2],   wpk[di * 5 + 2], a0);
        a1 = fma2(*(const u64*)&orr[y + 2],  wpk[di * 5 + 3], a1);
        a0 = fma2(*(const u64*)&er[y + 4],   wpk[di * 5 + 4], a0);
    }
    float2 r2 = upk(add2(a0, a1));
    *(float2*)&out[plane * 9216 + (x0 + xr) * 96 + y] = r2;
}

// ---------------------------------------------------------------------------
extern "C" void kernel_launch(void* const* d_in, const int* in_sizes, int n_in,
                              void* d_out, int out_size) {
    const float* h       = (const float*)d_in[0];
    const float* conv0_w = (const float*)d_in[1];
    const float* conv0_b = (const float*)d_in[2];
    const float* bn0_g   = (const float*)d_in[3];
    const float* bn0_b   = (const float*)d_in[4];
    const float* bn1_g   = (const float*)d_in[5];
    const float* bn1_b   = (const float*)d_in[6];
    const float* in_w    = (const float*)d_in[7];
    const float* in_b    = (const float*)d_in[8];
    const float* out_w   = (const float*)d_in[9];
    const float* out_b   = (const float*)d_in[10];
    const float* c1_w    = (const float*)d_in[11];
    const float* c1_b    = (const float*)d_in[12];
    float* out = (float*)d_out;

    cudaFuncSetAttribute(k_qkv,  cudaFuncAttributeMaxDynamicSharedMemorySize, 181248);
    cudaFuncSetAttribute(k_attn, cudaFuncAttributeMaxDynamicSharedMemorySize, 156 * 1024);

    k_conv0<<<dim3(96, 32), 256>>>(h, conv0_w, conv0_b);
    k_stats<<<dim3(64, 72), 256>>>(0);
    k_finalize<<<1, 64>>>(0, bn0_g, bn0_b);
    k_qkv<<<dim3(36, 32), 256, 181248>>>(in_w, in_b);
    k_attn<<<2304, 256, 154624>>>(out_w, out_b);
    k_stats<<<dim3(64, 72), 256>>>(1);
    k_finalize<<<1, 64>>>(1, bn1_g, bn1_b);
    k_mred<<<2048, 256>>>();
    k_kern<<<1, 256>>>(c1_w, c1_b);
    k_dyn<<<dim3(12, 2048), 384>>>(h, out);   // FIX: 384 threads (8 x-rows * 48 y-pairs)
}

// round 14
// speedup vs baseline: 1.0253x; 1.0253x over previous
#include <cuda_runtime.h>
#include <math.h>

typedef unsigned long long u64;

// Packed fp32x2 helpers (SASS FFMA2 path — only reachable via PTX)
__device__ __forceinline__ u64 pk(float lo, float hi) {
    u64 r; asm("mov.b64 %0, {%1, %2};" : "=l"(r) : "f"(lo), "f"(hi)); return r;
}
__device__ __forceinline__ float2 upk(u64 v) {
    float2 r; asm("mov.b64 {%0, %1}, %2;" : "=f"(r.x), "=f"(r.y) : "l"(v)); return r;
}
__device__ __forceinline__ u64 fma2(u64 a, u64 b, u64 c) {
    u64 d; asm("fma.rn.f32x2 %0, %1, %2, %3;" : "=l"(d) : "l"(a), "l"(b), "l"(c)); return d;
}
__device__ __forceinline__ u64 add2(u64 a, u64 b) {
    u64 d; asm("add.rn.f32x2 %0, %1, %2;" : "=l"(d) : "l"(a), "l"(b)); return d;
}

// Problem dims
#define VOL 18874368       // 4*64*8*96*96

// Scratch (device globals: the sanctioned no-alloc workaround)
__device__ float g_xc[VOL];      // conv0 output (pre-BN)
__device__ float g_q[VOL];       // [t][c][n]
__device__ float g_k[VOL];
__device__ float g_v[VOL];
__device__ float g_s[VOL];       // x + attn_out (pre-BN1)
__device__ float g_part[2 * 64 * 72];
__device__ float g_bn0[128];     // a[64], shift[64]
__device__ float g_bn1[128];
__device__ float g_m[2048];      // [b][c][t]
__device__ float g_w5[800];      // [b][t][25]

__device__ __forceinline__ float leaky(float v) { return v >= 0.f ? v : 0.01f * v; }

// ---------------------------------------------------------------------------
// K1: conv0 (3x3, pad 1, 64->64) -> g_xc, packed f32x2 FMAs (dual-copy rows).
// ---------------------------------------------------------------------------
__global__ __launch_bounds__(256) void k_conv0(const float* __restrict__ h,
                                               const float* __restrict__ w,
                                               const float* __restrict__ bias) {
    __shared__ __align__(16) float se[3][104];   // se[r][j] = v(j)
    __shared__ __align__(16) float so[3][104];   // so[r][j] = v(j+1)
    __shared__ float w_s[576];
    int bt = blockIdx.y;
    int b = bt >> 3, t = bt & 7;
    int x = blockIdx.x;
    int co = threadIdx.x & 63;
    int yg = threadIdx.x >> 6;
    int ybase = yg * 24;

    u64 acc[12];
#pragma unroll
    for (int i = 0; i < 12; i++) acc[i] = 0ULL;

    const float* hp = h + ((long)(b * 64) * 8 + t) * 9216;  // + ci*73728

    for (int ci = 0; ci < 64; ci++) {
        __syncthreads();
        for (int i = threadIdx.x; i < 294; i += 256) {
            int r = i / 98, yy = i - r * 98;
            int gx = x + r - 1, gy = yy - 1;
            float v = 0.f;
            if ((unsigned)gx < 96u && (unsigned)gy < 96u)
                v = hp[ci * 73728 + gx * 96 + gy];
            se[r][yy] = v;
            if (yy) so[r][yy - 1] = v;
        }
        for (int i = threadIdx.x; i < 576; i += 256) {
            int o = i / 9, k = i - o * 9;
            w_s[i] = w[(o * 64 + ci) * 9 + k];
        }
        __syncthreads();

        float wr[9];
#pragma unroll
        for (int k = 0; k < 9; k++) wr[k] = w_s[co * 9 + k];

#pragma unroll
        for (int r = 0; r < 3; r++) {
            u64 W0 = pk(wr[r * 3], wr[r * 3]);
            u64 W1 = pk(wr[r * 3 + 1], wr[r * 3 + 1]);
            u64 W2 = pk(wr[r * 3 + 2], wr[r * 3 + 2]);
            const u64* pe = (const u64*)&se[r][ybase];
            const u64* po = (const u64*)&so[r][ybase];
#pragma unroll
            for (int j = 0; j < 12; j++) {
                acc[j] = fma2(pe[j],     W0, acc[j]);
                acc[j] = fma2(po[j],     W1, acc[j]);
                acc[j] = fma2(pe[j + 1], W2, acc[j]);
            }
        }
    }
    float bb = bias[co];
    float* op = g_xc + ((b * 64 + co) * 8 + t) * 9216 + x * 96 + ybase;
#pragma unroll
    for (int j = 0; j < 12; j++) {
        float2 v = upk(acc[j]);
        float2 r2; r2.x = v.x + bb; r2.y = v.y + bb;
        *(float2*)&op[2 * j] = r2;
    }
}

// ---------------------------------------------------------------------------
// K2: per-channel sum / sumsq partials (deterministic two-stage reduction)
// ---------------------------------------------------------------------------
__global__ __launch_bounds__(256) void k_stats(int which) {
    const float* src = which ? g_s : g_xc;
    int c = blockIdx.x;
    int chunk = blockIdx.y;
    float s = 0.f, q = 0.f;
    for (int i = threadIdx.x; i < 4096; i += 256) {
        int j = chunk * 4096 + i;
        int b = j / 73728;
        int r = j - b * 73728;
        float v = src[(b * 64 + c) * 73728 + r];
        s += v; q += v * v;
    }
    __shared__ float rs[256], rq[256];
    rs[threadIdx.x] = s; rq[threadIdx.x] = q;
    __syncthreads();
    for (int st = 128; st > 0; st >>= 1) {
        if (threadIdx.x < st) { rs[threadIdx.x] += rs[threadIdx.x + st];
                                rq[threadIdx.x] += rq[threadIdx.x + st]; }
        __syncthreads();
    }
    if (threadIdx.x == 0) {
        g_part[c * 72 + chunk] = rs[0];
        g_part[4608 + c * 72 + chunk] = rq[0];
    }
}

__global__ void k_finalize(int which, const float* __restrict__ gamma,
                           const float* __restrict__ beta) {
    int c = threadIdx.x;  // 64 threads
    float s = 0.f, q = 0.f;
    for (int i = 0; i < 72; i++) { s += g_part[c * 72 + i]; q += g_part[4608 + c * 72 + i]; }
    float mean = s * (1.f / 294912.f);
    float var = q * (1.f / 294912.f) - mean * mean;
    float a = gamma[c] * rsqrtf(var + 1e-5f);
    float* dst = which ? g_bn1 : g_bn0;
    dst[c] = a;
    dst[64 + c] = beta[c] - mean * a;
}

// ---------------------------------------------------------------------------
// K3: QKV projection with f32x2, occupancy-friendly (83KB smem -> 2 CTA/SM).
// Block = 128 positions. Activations duplicated ((x,x) pairs, 64KB); weights
// loaded PER PHASE (64 outs, 17KB). Outputs paired: weight pairs are free
// LDS.128 from the row-major w tile. Thread: 4 out-pairs x 4 positions,
// positions interleaved stride-32 (conflict-free LDS.64, coalesced STG).
// Inner loop per c: 4 LDS.64 + 2 LDS.128(broadcast) + 16 fma2.
// ---------------------------------------------------------------------------
__global__ __launch_bounds__(256) void k_qkv(const float* __restrict__ W,
                                             const float* __restrict__ Wb) {
    extern __shared__ __align__(16) float sm[];
    float* in_d = sm;                 // 64 * 256 floats (dup pairs) = 64KB
    float* w_s  = sm + 16384;         // 64 * 68 floats (one phase)   = 17KB
    int bt = blockIdx.y;
    int b = bt >> 3, t = bt & 7;
    int s0 = blockIdx.x * 128;

    // Fill duplicated activations for 128 positions
    for (int i = threadIdx.x; i < 2048; i += 256) {
        int c = i >> 5, g = (i & 31) * 4;
        float4 v4 = *(const float4*)&g_xc[((b * 64 + c) * 8 + t) * 9216 + s0 + g];
        float a = g_bn0[c], sh = g_bn0[64 + c];
        float e0 = leaky(a * v4.x + sh);
        float e1 = leaky(a * v4.y + sh);
        float e2 = leaky(a * v4.z + sh);
        float e3 = leaky(a * v4.w + sh);
        u64* dst = (u64*)(in_d + c * 256 + 2 * g);
        dst[0] = pk(e0, e0); dst[1] = pk(e1, e1);
        dst[2] = pk(e2, e2); dst[3] = pk(e3, e3);
    }

    int pg = threadIdx.x & 31;
    int og = threadIdx.x >> 5;

    for (int p = 0; p < 3; p++) {
        // Load this phase's 64x64 weight tile, transposed: w_s[c][o]
        __syncthreads();
        for (int i = threadIdx.x; i < 4096; i += 256) {
            int o = i >> 6, c = i & 63;
            w_s[c * 68 + o] = W[(p * 64 + o) * 64 + c];
        }
        __syncthreads();

        u64 acc[4][4];
#pragma unroll
        for (int i = 0; i < 4; i++)
#pragma unroll
            for (int j = 0; j < 4; j++) acc[i][j] = 0ULL;

        for (int c = 0; c < 64; c++) {
            const u64* xrow = (const u64*)(in_d + c * 256);
            u64 xv[4];
#pragma unroll
            for (int j = 0; j < 4; j++) xv[j] = xrow[pg + 32 * j];
            const u64* wp = (const u64*)&w_s[c * 68 + og * 8];
            u64 w01 = wp[0], w23 = wp[1], w45 = wp[2], w67 = wp[3];
#pragma unroll
            for (int j = 0; j < 4; j++) {
                acc[0][j] = fma2(w01, xv[j], acc[0][j]);
                acc[1][j] = fma2(w23, xv[j], acc[1][j]);
                acc[2][j] = fma2(w45, xv[j], acc[2][j]);
                acc[3][j] = fma2(w67, xv[j], acc[3][j]);
            }
        }
        float* dst = (p == 0) ? g_q : (p == 1 ? g_k : g_v);
        float scale = (p == 0) ? 0.35355339059327373f : 1.f;
#pragma unroll
        for (int i = 0; i < 4; i++) {
            int o0 = og * 8 + 2 * i;
            float b0 = Wb[p * 64 + o0], b1 = Wb[p * 64 + o0 + 1];
            long base0 = (long)(t * 64 + o0) * 36864 + b * 9216 + s0 + pg;
            long base1 = base0 + 36864;
#pragma unroll
            for (int j = 0; j < 4; j++) {
                float2 v = upk(acc[i][j]);
                dst[base0 + 32 * j] = (v.x + b0) * scale;
                dst[base1 + 32 * j] = (v.y + b1) * scale;
            }
        }
    }
}

// ---------------------------------------------------------------------------
// K4: attention core + out-proj + residual -> g_s  (phase C = scalar, R8 form)
// ---------------------------------------------------------------------------
__global__ __launch_bounds__(256) void k_attn(const float* __restrict__ Wo,
                                              const float* __restrict__ bo) {
    extern __shared__ __align__(16) float sm[];
    float* q_s  = sm;              // 512*17 = 8704
    float* k_s  = sm + 8704;
    float* v_s  = sm + 17408;
    float* o_s  = sm + 26112;      // 16*516 = 8256
    float* wo_s = sm + 34368;      // 4096
    float* ab_s = sm + 38464;      // 128
    float* bo_s = sm + 38592;      // 64

    int n0 = blockIdx.x * 16;
    int b = n0 / 9216;
    int s0 = n0 - b * 9216;

    for (int i = threadIdx.x; i < 8192; i += 256) {
        int tc = i >> 4, nl = i & 15;
        int ga = tc * 36864 + n0 + nl;
        q_s[tc * 17 + nl] = g_q[ga];
        k_s[tc * 17 + nl] = g_k[ga];
        v_s[tc * 17 + nl] = g_v[ga];
    }
    for (int i = threadIdx.x; i < 4096; i += 256) wo_s[i] = Wo[i];
    if (threadIdx.x < 128) ab_s[threadIdx.x] = g_bn0[threadIdx.x];
    else if (threadIdx.x < 192) bo_s[threadIdx.x - 128] = bo[threadIdx.x - 128];
    __syncthreads();

    // Phase B: per-(token, head) attention over T=8
    {
        int u = threadIdx.x >> 7;
        int rem = threadIdx.x & 127;
        int nl = rem & 15;
        int hh = rem >> 4;
#pragma unroll
        for (int qi = 0; qi < 4; qi++) {
            int qt = u * 4 + qi;
            float qr[8];
#pragma unroll
            for (int d = 0; d < 8; d++) qr[d] = q_s[(qt * 64 + hh * 8 + d) * 17 + nl];
            float sc[8];
#pragma unroll
            for (int kt = 0; kt < 8; kt++) {
                float s = 0.f;
#pragma unroll
                for (int d = 0; d < 8; d++)
                    s = fmaf(qr[d], k_s[(kt * 64 + hh * 8 + d) * 17 + nl], s);
                sc[kt] = s;
            }
            float mx = sc[0];
#pragma unroll
            for (int kt = 1; kt < 8; kt++) mx = fmaxf(mx, sc[kt]);
            float sum = 0.f;
#pragma unroll
            for (int kt = 0; kt < 8; kt++) { sc[kt] = __expf(sc[kt] - mx); sum += sc[kt]; }
            float inv = 1.f / sum;
#pragma unroll
            for (int d = 0; d < 8; d++) {
                float o = 0.f;
#pragma unroll
                for (int kt = 0; kt < 8; kt++)
                    o = fmaf(sc[kt], v_s[(kt * 64 + hh * 8 + d) * 17 + nl], o);
                o_s[nl * 516 + qt * 64 + hh * 8 + d] = o * inv;
            }
        }
    }
    __syncthreads();

    // Phase C: out-proj + residual (x = leaky(bn0(xc))) -> g_s   [R8 scalar]
    for (int idx = threadIdx.x; idx < 8192; idx += 256) {
        int nl = idx & 15;
        int co = (idx >> 4) & 63;
        int t = idx >> 10;
        float acc = bo_s[co];
        const float* orow = &o_s[nl * 516 + t * 64];
        const float* wrow = &wo_s[co * 64];
#pragma unroll
        for (int c = 0; c < 64; c += 4) {
            float4 ov = *(const float4*)&orow[c];
            float4 wv = *(const float4*)&wrow[c];
            acc = fmaf(ov.x, wv.x, acc);
            acc = fmaf(ov.y, wv.y, acc);
            acc = fmaf(ov.z, wv.z, acc);
            acc = fmaf(ov.w, wv.w, acc);
        }
        int ga = ((b * 64 + co) * 8 + t) * 9216 + s0 + nl;
        float x = leaky(ab_s[co] * g_xc[ga] + ab_s[64 + co]);
        g_s[ga] = x + acc;
    }
}

// ---------------------------------------------------------------------------
// K6: m[b,c,t] = spatial mean of leaky(bn1(g_s))
// ---------------------------------------------------------------------------
__global__ __launch_bounds__(256) void k_mred() {
    int bct = blockIdx.x;
    int c = (bct >> 3) & 63;
    float a = g_bn1[c], sh = g_bn1[64 + c];
    const float* p = g_s + bct * 9216;
    float s = 0.f;
    for (int i = threadIdx.x; i < 9216; i += 256) s += leaky(a * p[i] + sh);
    __shared__ float rs[256];
    rs[threadIdx.x] = s;
    __syncthreads();
    for (int st = 128; st > 0; st >>= 1) {
        if (threadIdx.x < st) rs[threadIdx.x] += rs[threadIdx.x + st];
        __syncthreads();
    }
    if (threadIdx.x == 0) g_m[bct] = rs[0] * (1.f / 9216.f);
}

// ---------------------------------------------------------------------------
// K7: per-(b,t) 5x5 kernels
// ---------------------------------------------------------------------------
__global__ void k_kern(const float* __restrict__ w1, const float* __restrict__ b1) {
    for (int i = threadIdx.x; i < 800; i += 256) {
        int b = i / 200;
        int rem = i - b * 200;
        int o = rem / 8;
        int t = rem - o * 8;
        float s = b1[o];
        for (int c = 0; c < 64; c++)
            s = fmaf(w1[o * 64 + c], g_m[(b * 64 + c) * 8 + t], s);
        g_w5[(b * 8 + t) * 25 + o] = s;
    }
}

// ---------------------------------------------------------------------------
// K8: dynamic depthwise 5x5 conv with f32x2 y-pairs (dual-copy smem rows)
// 384 thr: 8 x-rows x 48 y-pairs, one pair per thread.
// ---------------------------------------------------------------------------
__global__ __launch_bounds__(384) void k_dyn(const float* __restrict__ h,
                                             float* __restrict__ out) {
    __shared__ __align__(16) float se[12][104];
    __shared__ __align__(16) float so[12][104];
    __shared__ float w_s[25];
    int plane = blockIdx.y;          // (b*64+c)*8+t
    int b = plane >> 9;
    int t = plane & 7;
    int bt = b * 8 + t;
    int x0 = blockIdx.x * 8;

    if (threadIdx.x < 25) w_s[threadIdx.x] = g_w5[bt * 25 + threadIdx.x];
    for (int i = threadIdx.x; i < 1200; i += 384) {
        int r = i / 100, c = i - r * 100;
        int gx = x0 + r - 2, gy = c - 2;
        float v = 0.f;
        if ((unsigned)gx < 96u && (unsigned)gy < 96u)
            v = h[plane * 9216 + gx * 96 + gy];
        se[r][c] = v;
        if (c) so[r][c - 1] = v;
    }
    __syncthreads();

    int xr = threadIdx.x / 48;
    int y = (threadIdx.x - xr * 48) * 2;
    u64 wpk[25];
#pragma unroll
    for (int i = 0; i < 25; i++) { float wv = w_s[i]; wpk[i] = pk(wv, wv); }

    u64 a0 = 0ULL, a1 = 0ULL;
#pragma unroll
    for (int di = 0; di < 5; di++) {
        const float* er  = se[xr + di];
        const float* orr = so[xr + di];
        a0 = fma2(*(const u64*)&er[y],       wpk[di * 5 + 0], a0);
        a1 = fma2(*(const u64*)&orr[y],      wpk[di * 5 + 1], a1);
        a0 = fma2(*(const u64*)&er[y + 2],   wpk[di * 5 + 2], a0);
        a1 = fma2(*(const u64*)&orr[y + 2],  wpk[di * 5 + 3], a1);
        a0 = fma2(*(const u64*)&er[y + 4],   wpk[di * 5 + 4], a0);
    }
    float2 r2 = upk(add2(a0, a1));
    *(float2*)&out[plane * 9216 + (x0 + xr) * 96 + y] = r2;
}

// ---------------------------------------------------------------------------
extern "C" void kernel_launch(void* const* d_in, const int* in_sizes, int n_in,
                              void* d_out, int out_size) {
    const float* h       = (const float*)d_in[0];
    const float* conv0_w = (const float*)d_in[1];
    const float* conv0_b = (const float*)d_in[2];
    const float* bn0_g   = (const float*)d_in[3];
    const float* bn0_b   = (const float*)d_in[4];
    const float* bn1_g   = (const float*)d_in[5];
    const float* bn1_b   = (const float*)d_in[6];
    const float* in_w    = (const float*)d_in[7];
    const float* in_b    = (const float*)d_in[8];
    const float* out_w   = (const float*)d_in[9];
    const float* out_b   = (const float*)d_in[10];
    const float* c1_w    = (const float*)d_in[11];
    const float* c1_b    = (const float*)d_in[12];
    float* out = (float*)d_out;

    // in_d 64KB + w_s 64*68*4 = 17408B -> 82944B dynamic => 2 CTA/SM
    cudaFuncSetAttribute(k_qkv,  cudaFuncAttributeMaxDynamicSharedMemorySize, 82944);
    cudaFuncSetAttribute(k_attn, cudaFuncAttributeMaxDynamicSharedMemorySize, 156 * 1024);

    k_conv0<<<dim3(96, 32), 256>>>(h, conv0_w, conv0_b);
    k_stats<<<dim3(64, 72), 256>>>(0);
    k_finalize<<<1, 64>>>(0, bn0_g, bn0_b);
    k_qkv<<<dim3(72, 32), 256, 82944>>>(in_w, in_b);
    k_attn<<<2304, 256, 154624>>>(out_w, out_b);
    k_stats<<<dim3(64, 72), 256>>>(1);
    k_finalize<<<1, 64>>>(1, bn1_g, bn1_b);
    k_mred<<<2048, 256>>>();
    k_kern<<<1, 256>>>(c1_w, c1_b);
    k_dyn<<<dim3(12, 2048), 384>>>(h, out);
}

// round 15
// speedup vs baseline: 1.1249x; 1.0971x over previous
#include <cuda_runtime.h>
#include <math.h>

typedef unsigned long long u64;

// Packed fp32x2 helpers (SASS FFMA2 path — only reachable via PTX)
__device__ __forceinline__ u64 pk(float lo, float hi) {
    u64 r; asm("mov.b64 %0, {%1, %2};" : "=l"(r) : "f"(lo), "f"(hi)); return r;
}
__device__ __forceinline__ float2 upk(u64 v) {
    float2 r; asm("mov.b64 {%0, %1}, %2;" : "=f"(r.x), "=f"(r.y) : "l"(v)); return r;
}
__device__ __forceinline__ u64 fma2(u64 a, u64 b, u64 c) {
    u64 d; asm("fma.rn.f32x2 %0, %1, %2, %3;" : "=l"(d) : "l"(a), "l"(b), "l"(c)); return d;
}

// Problem dims
#define VOL 18874368       // 4*64*8*96*96

// Scratch (device globals: the sanctioned no-alloc workaround)
__device__ float g_xc[VOL];      // conv0 output (pre-BN)
__device__ float g_q[VOL];       // [t][c][n]
__device__ float g_k[VOL];
__device__ float g_v[VOL];
__device__ float g_s[VOL];      // x + attn_out (pre-BN1)
__device__ float g_part[2 * 64 * 72];
__device__ float g_bn0[128];     // a[64], shift[64]
__device__ float g_bn1[128];
__device__ float g_m[2048];      // [b][c][t]
__device__ float g_w5[800];      // [b][t][25]

__device__ __forceinline__ float leaky(float v) { return v >= 0.f ? v : 0.01f * v; }

// ---------------------------------------------------------------------------
// K1: conv0  (3x3 over X,Y; pad 1; 64->64 channels) -> g_xc   [R8 scalar form]
// ---------------------------------------------------------------------------
__global__ __launch_bounds__(256) void k_conv0(const float* __restrict__ h,
                                               const float* __restrict__ w,
                                               const float* __restrict__ bias) {
    __shared__ __align__(16) float in_s[3][100];
    __shared__ float w_s[576];
    int bt = blockIdx.y;
    int b = bt >> 3, t = bt & 7;
    int x = blockIdx.x;
    int co = threadIdx.x & 63;
    int yg = threadIdx.x >> 6;
    int ybase = yg * 24;

    float acc[24];
#pragma unroll
    for (int i = 0; i < 24; i++) acc[i] = 0.f;

    const float* hp = h + ((long)(b * 64) * 8 + t) * 9216;  // + ci*73728

    for (int ci = 0; ci < 64; ci++) {
        __syncthreads();
        for (int i = threadIdx.x; i < 294; i += 256) {
            int r = i / 98, yy = i - r * 98;
            int gx = x + r - 1, gy = yy - 1;
            float v = 0.f;
            if ((unsigned)gx < 96u && (unsigned)gy < 96u)
                v = hp[ci * 73728 + gx * 96 + gy];
            in_s[r][yy] = v;
        }
        for (int i = threadIdx.x; i < 576; i += 256) {
            int o = i / 9, k = i - o * 9;
            w_s[i] = w[(o * 64 + ci) * 9 + k];
        }
        __syncthreads();

        float wr[9];
#pragma unroll
        for (int k = 0; k < 9; k++) wr[k] = w_s[co * 9 + k];

#pragma unroll
        for (int r = 0; r < 3; r++) {
            float v[26];
#pragma unroll
            for (int j = 0; j < 26; j++) v[j] = in_s[r][ybase + j];
#pragma unroll
            for (int y = 0; y < 24; y++)
                acc[y] = fmaf(v[y], wr[r * 3],
                          fmaf(v[y + 1], wr[r * 3 + 1],
                           fmaf(v[y + 2], wr[r * 3 + 2], acc[y])));
        }
    }
    float bb = bias[co];
    float* op = g_xc + ((b * 64 + co) * 8 + t) * 9216 + x * 96 + ybase;
#pragma unroll
    for (int y = 0; y < 24; y++) op[y] = acc[y] + bb;
}

// ---------------------------------------------------------------------------
// K2: per-channel sum / sumsq partials (deterministic two-stage reduction)
// ---------------------------------------------------------------------------
__global__ __launch_bounds__(256) void k_stats(int which) {
    const float* src = which ? g_s : g_xc;
    int c = blockIdx.x;
    int chunk = blockIdx.y;
    float s = 0.f, q = 0.f;
    for (int i = threadIdx.x; i < 4096; i += 256) {
        int j = chunk * 4096 + i;
        int b = j / 73728;
        int r = j - b * 73728;
        float v = src[(b * 64 + c) * 73728 + r];
        s += v; q += v * v;
    }
    __shared__ float rs[256], rq[256];
    rs[threadIdx.x] = s; rq[threadIdx.x] = q;
    __syncthreads();
    for (int st = 128; st > 0; st >>= 1) {
        if (threadIdx.x < st) { rs[threadIdx.x] += rs[threadIdx.x + st];
                                rq[threadIdx.x] += rq[threadIdx.x + st]; }
        __syncthreads();
    }
    if (threadIdx.x == 0) {
        g_part[c * 72 + chunk] = rs[0];
        g_part[4608 + c * 72 + chunk] = rq[0];
    }
}

__global__ void k_finalize(int which, const float* __restrict__ gamma,
                           const float* __restrict__ beta) {
    int c = threadIdx.x;  // 64 threads
    float s = 0.f, q = 0.f;
    for (int i = 0; i < 72; i++) { s += g_part[c * 72 + i]; q += g_part[4608 + c * 72 + i]; }
    float mean = s * (1.f / 294912.f);
    float var = q * (1.f / 294912.f) - mean * mean;
    float a = gamma[c] * rsqrtf(var + 1e-5f);
    float* dst = which ? g_bn1 : g_bn0;
    dst[c] = a;
    dst[64 + c] = beta[c] - mean * a;
}

// ---------------------------------------------------------------------------
// K3: QKV projection, diagonal-pair FFMA2 (no operand duplication).
// Per (b,t): Out[192][9216] = W[192][64] @ leaky(bn0(xc)).
// Block = 128 positions (64 pos-pairs). x stored naturally (32KB), W stored
// transposed w_s[c][o] (50KB) so weight PAIRS are natural LDS.128 broadcasts.
// Thread (og=warp, pg=lane): 8 outs (4 out-pairs) x 2 pos-pairs.
// Per c: 2 LDS.64 (x pairs) + 2 LDS.128 bcast (w pairs) + 16 fma2.
// Diagonal accumulators: accA = sum w01*(x0,x1), accB = sum w01*(x1,x0);
// unscrambled only in the epilogue. Coalesced STG.64 stores.
// ---------------------------------------------------------------------------
__global__ __launch_bounds__(256) void k_qkv(const float* __restrict__ W,
                                             const float* __restrict__ Wb) {
    extern __shared__ __align__(16) float sm[];
    float* x_s = sm;                  // 64 * 128 floats = 32KB
    float* w_s = sm + 8192;           // 64 * 196 floats (transposed, padded)
    int bt = blockIdx.y;
    int b = bt >> 3, t = bt & 7;
    int s0 = blockIdx.x * 128;

    for (int i = threadIdx.x; i < 12288; i += 256) {
        int o = i >> 6, c = i & 63;
        w_s[c * 196 + o] = W[i];
    }
    for (int i = threadIdx.x; i < 2048; i += 256) {
        int c = i >> 5, g = (i & 31) * 4;
        float4 v4 = *(const float4*)&g_xc[((b * 64 + c) * 8 + t) * 9216 + s0 + g];
        float a = g_bn0[c], sh = g_bn0[64 + c];
        float4 r4;
        r4.x = leaky(a * v4.x + sh);
        r4.y = leaky(a * v4.y + sh);
        r4.z = leaky(a * v4.z + sh);
        r4.w = leaky(a * v4.w + sh);
        *(float4*)&x_s[c * 128 + g] = r4;
    }
    __syncthreads();

    int pg = threadIdx.x & 31;
    int og = threadIdx.x >> 5;

    for (int p = 0; p < 3; p++) {
        u64 accA[4][2], accB[4][2];
#pragma unroll
        for (int i = 0; i < 4; i++)
#pragma unroll
            for (int j = 0; j < 2; j++) { accA[i][j] = 0ULL; accB[i][j] = 0ULL; }

        for (int c = 0; c < 64; c++) {
            float2 xa = *(const float2*)&x_s[c * 128 + 2 * pg];        // pos pair j=0
            float2 xb = *(const float2*)&x_s[c * 128 + 2 * pg + 64];   // pos pair j=1
            u64 xaN = pk(xa.x, xa.y), xaS = pk(xa.y, xa.x);
            u64 xbN = pk(xb.x, xb.y), xbS = pk(xb.y, xb.x);
            const u64* wp = (const u64*)&w_s[c * 196 + p * 64 + og * 8];
            u64 w0 = wp[0], w1 = wp[1], w2 = wp[2], w3 = wp[3];
            accA[0][0] = fma2(w0, xaN, accA[0][0]);
            accB[0][0] = fma2(w0, xaS, accB[0][0]);
            accA[0][1] = fma2(w0, xbN, accA[0][1]);
            accB[0][1] = fma2(w0, xbS, accB[0][1]);
            accA[1][0] = fma2(w1, xaN, accA[1][0]);
            accB[1][0] = fma2(w1, xaS, accB[1][0]);
            accA[1][1] = fma2(w1, xbN, accA[1][1]);
            accB[1][1] = fma2(w1, xbS, accB[1][1]);
            accA[2][0] = fma2(w2, xaN, accA[2][0]);
            accB[2][0] = fma2(w2, xaS, accB[2][0]);
            accA[2][1] = fma2(w2, xbN, accA[2][1]);
            accB[2][1] = fma2(w2, xbS, accB[2][1]);
            accA[3][0] = fma2(w3, xaN, accA[3][0]);
            accB[3][0] = fma2(w3, xaS, accB[3][0]);
            accA[3][1] = fma2(w3, xbN, accA[3][1]);
            accB[3][1] = fma2(w3, xbS, accB[3][1]);
        }

        float* dst = (p == 0) ? g_q : (p == 1 ? g_k : g_v);
        float scale = (p == 0) ? 0.35355339059327373f : 1.f;
#pragma unroll
        for (int i = 0; i < 4; i++) {
            int o0 = og * 8 + 2 * i;           // within-phase out row (even)
            float b0 = Wb[p * 64 + o0], b1 = Wb[p * 64 + o0 + 1];
            long r0 = (long)(t * 64 + o0) * 36864 + b * 9216 + s0 + 2 * pg;
            long r1 = r0 + 36864;
#pragma unroll
            for (int j = 0; j < 2; j++) {
                float2 A = upk(accA[i][j]);    // (o0@p0, o1@p1)
                float2 Bv = upk(accB[i][j]);   // (o0@p1, o1@p0)
                float2 e0, e1;
                e0.x = (A.x + b0) * scale;  e0.y = (Bv.x + b0) * scale;  // row o0: p0,p1
                e1.x = (Bv.y + b1) * scale; e1.y = (A.y + b1) * scale;   // row o1: p0,p1
                *(float2*)&dst[r0 + 64 * j] = e0;
                *(float2*)&dst[r1 + 64 * j] = e1;
            }
        }
    }
}

// ---------------------------------------------------------------------------
// K4: attention core + out-proj + residual -> g_s    [R8 form]
// ---------------------------------------------------------------------------
__global__ __launch_bounds__(256) void k_attn(const float* __restrict__ Wo,
                                              const float* __restrict__ bo) {
    extern __shared__ __align__(16) float sm[];
    float* q_s  = sm;              // 512*17 = 8704
    float* k_s  = sm + 8704;
    float* v_s  = sm + 17408;
    float* o_s  = sm + 26112;      // 16*516 = 8256
    float* wo_s = sm + 34368;      // 4096
    float* ab_s = sm + 38464;      // 128
    float* bo_s = sm + 38592;      // 64

    int n0 = blockIdx.x * 16;
    int b = n0 / 9216;
    int s0 = n0 - b * 9216;

    for (int i = threadIdx.x; i < 8192; i += 256) {
        int tc = i >> 4, nl = i & 15;
        int ga = tc * 36864 + n0 + nl;
        q_s[tc * 17 + nl] = g_q[ga];
        k_s[tc * 17 + nl] = g_k[ga];
        v_s[tc * 17 + nl] = g_v[ga];
    }
    for (int i = threadIdx.x; i < 4096; i += 256) wo_s[i] = Wo[i];
    if (threadIdx.x < 128) ab_s[threadIdx.x] = g_bn0[threadIdx.x];
    else if (threadIdx.x < 192) bo_s[threadIdx.x - 128] = bo[threadIdx.x - 128];
    __syncthreads();

    // Phase B: per-(token, head) attention over T=8
    {
        int u = threadIdx.x >> 7;
        int rem = threadIdx.x & 127;
        int nl = rem & 15;
        int hh = rem >> 4;
#pragma unroll
        for (int qi = 0; qi < 4; qi++) {
            int qt = u * 4 + qi;
            float qr[8];
#pragma unroll
            for (int d = 0; d < 8; d++) qr[d] = q_s[(qt * 64 + hh * 8 + d) * 17 + nl];
            float sc[8];
#pragma unroll
            for (int kt = 0; kt < 8; kt++) {
                float s = 0.f;
#pragma unroll
                for (int d = 0; d < 8; d++)
                    s = fmaf(qr[d], k_s[(kt * 64 + hh * 8 + d) * 17 + nl], s);
                sc[kt] = s;
            }
            float mx = sc[0];
#pragma unroll
            for (int kt = 1; kt < 8; kt++) mx = fmaxf(mx, sc[kt]);
            float sum = 0.f;
#pragma unroll
            for (int kt = 0; kt < 8; kt++) { sc[kt] = __expf(sc[kt] - mx); sum += sc[kt]; }
            float inv = 1.f / sum;
#pragma unroll
            for (int d = 0; d < 8; d++) {
                float o = 0.f;
#pragma unroll
                for (int kt = 0; kt < 8; kt++)
                    o = fmaf(sc[kt], v_s[(kt * 64 + hh * 8 + d) * 17 + nl], o);
                o_s[nl * 516 + qt * 64 + hh * 8 + d] = o * inv;
            }
        }
    }
    __syncthreads();

    // Phase C: out-proj + residual (x = leaky(bn0(xc))) -> g_s
    for (int idx = threadIdx.x; idx < 8192; idx += 256) {
        int nl = idx & 15;
        int co = (idx >> 4) & 63;
        int t = idx >> 10;
        float acc = bo_s[co];
        const float* orow = &o_s[nl * 516 + t * 64];
        const float* wrow = &wo_s[co * 64];
#pragma unroll
        for (int c = 0; c < 64; c += 4) {
            float4 ov = *(const float4*)&orow[c];
            float4 wv = *(const float4*)&wrow[c];
            acc = fmaf(ov.x, wv.x, acc);
            acc = fmaf(ov.y, wv.y, acc);
            acc = fmaf(ov.z, wv.z, acc);
            acc = fmaf(ov.w, wv.w, acc);
        }
        int ga = ((b * 64 + co) * 8 + t) * 9216 + s0 + nl;
        float x = leaky(ab_s[co] * g_xc[ga] + ab_s[64 + co]);
        g_s[ga] = x + acc;
    }
}

// ---------------------------------------------------------------------------
// K6: m[b,c,t] = spatial mean of leaky(bn1(g_s))
// ---------------------------------------------------------------------------
__global__ __launch_bounds__(256) void k_mred() {
    int bct = blockIdx.x;
    int c = (bct >> 3) & 63;
    float a = g_bn1[c], sh = g_bn1[64 + c];
    const float* p = g_s + bct * 9216;
    float s = 0.f;
    for (int i = threadIdx.x; i < 9216; i += 256) s += leaky(a * p[i] + sh);
    __shared__ float rs[256];
    rs[threadIdx.x] = s;
    __syncthreads();
    for (int st = 128; st > 0; st >>= 1) {
        if (threadIdx.x < st) rs[threadIdx.x] += rs[threadIdx.x + st];
        __syncthreads();
    }
    if (threadIdx.x == 0) g_m[bct] = rs[0] * (1.f / 9216.f);
}

// ---------------------------------------------------------------------------
// K7: per-(b,t) 5x5 kernels
// ---------------------------------------------------------------------------
__global__ void k_kern(const float* __restrict__ w1, const float* __restrict__ b1) {
    for (int i = threadIdx.x; i < 800; i += 256) {
        int b = i / 200;
        int rem = i - b * 200;
        int o = rem / 8;
        int t = rem - o * 8;
        float s = b1[o];
        for (int c = 0; c < 64; c++)
            s = fmaf(w1[o * 64 + c], g_m[(b * 64 + c) * 8 + t], s);
        g_w5[(b * 8 + t) * 25 + o] = s;
    }
}

// ---------------------------------------------------------------------------
// K8: dynamic depthwise 5x5 conv -> d_out      [R8 scalar form]
// ---------------------------------------------------------------------------
__global__ __launch_bounds__(256) void k_dyn(const float* __restrict__ h,
                                             float* __restrict__ out) {
    __shared__ __align__(16) float in_s[12][100];
    __shared__ float w_s[25];
    int plane = blockIdx.y;          // (b*64+c)*8+t
    int b = plane >> 9;
    int t = plane & 7;
    int bt = b * 8 + t;
    int x0 = blockIdx.x * 8;

    if (threadIdx.x < 25) w_s[threadIdx.x] = g_w5[bt * 25 + threadIdx.x];
    for (int i = threadIdx.x; i < 1200; i += 256) {
        int r = i / 100, cc = i - r * 100;
        int gx = x0 + r - 2, gy = cc - 2;
        float v = 0.f;
        if ((unsigned)gx < 96u && (unsigned)gy < 96u)
            v = h[plane * 9216 + gx * 96 + gy];
        in_s[r][cc] = v;
    }
    __syncthreads();
    for (int o = threadIdx.x; o < 768; o += 256) {
        int xr = o / 96, y = o - xr * 96;
        float acc = 0.f;
#pragma unroll
        for (int di = 0; di < 5; di++)
#pragma unroll
            for (int dj = 0; dj < 5; dj++)
                acc = fmaf(in_s[xr + di][y + dj], w_s[di * 5 + dj], acc);
        out[plane * 9216 + (x0 + xr) * 96 + y] = acc;
    }
}

// ---------------------------------------------------------------------------
extern "C" void kernel_launch(void* const* d_in, const int* in_sizes, int n_in,
                              void* d_out, int out_size) {
    const float* h       = (const float*)d_in[0];
    const float* conv0_w = (const float*)d_in[1];
    const float* conv0_b = (const float*)d_in[2];
    const float* bn0_g   = (const float*)d_in[3];
    const float* bn0_b   = (const float*)d_in[4];
    const float* bn1_g   = (const float*)d_in[5];
    const float* bn1_b   = (const float*)d_in[6];
    const float* in_w    = (const float*)d_in[7];
    const float* in_b    = (const float*)d_in[8];
    const float* out_w   = (const float*)d_in[9];
    const float* out_b   = (const float*)d_in[10];
    const float* c1_w    = (const float*)d_in[11];
    const float* c1_b    = (const float*)d_in[12];
    float* out = (float*)d_out;

    // x_s 32768B + w_s 64*196*4 = 50176B -> 82944B dynamic => 2 CTA/SM
    cudaFuncSetAttribute(k_qkv,  cudaFuncAttributeMaxDynamicSharedMemorySize, 82944);
    cudaFuncSetAttribute(k_attn, cudaFuncAttributeMaxDynamicSharedMemorySize, 156 * 1024);

    k_conv0<<<dim3(96, 32), 256>>>(h, conv0_w, conv0_b);
    k_stats<<<dim3(64, 72), 256>>>(0);
    k_finalize<<<1, 64>>>(0, bn0_g, bn0_b);
    k_qkv<<<dim3(72, 32), 256, 82944>>>(in_w, in_b);
    k_attn<<<2304, 256, 154624>>>(out_w, out_b);
    k_stats<<<dim3(64, 72), 256>>>(1);
    k_finalize<<<1, 64>>>(1, bn1_g, bn1_b);
    k_mred<<<2048, 256>>>();
    k_kern<<<1, 256>>>(c1_w, c1_b);
    k_dyn<<<dim3(12, 2048), 256>>>(h, out);
}

// round 16
// speedup vs baseline: 1.2215x; 1.0859x over previous
#include <cuda_runtime.h>
#include <math.h>

typedef unsigned long long u64;

// Packed fp32x2 helpers (SASS FFMA2 path — only reachable via PTX)
__device__ __forceinline__ u64 pk(float lo, float hi) {
    u64 r; asm("mov.b64 %0, {%1, %2};" : "=l"(r) : "f"(lo), "f"(hi)); return r;
}
__device__ __forceinline__ float2 upk(u64 v) {
    float2 r; asm("mov.b64 {%0, %1}, %2;" : "=f"(r.x), "=f"(r.y) : "l"(v)); return r;
}
__device__ __forceinline__ u64 fma2(u64 a, u64 b, u64 c) {
    u64 d; asm("fma.rn.f32x2 %0, %1, %2, %3;" : "=l"(d) : "l"(a), "l"(b), "l"(c)); return d;
}

// Problem dims
#define VOL 18874368       // 4*64*8*96*96

// Scratch (device globals: the sanctioned no-alloc workaround)
__device__ float g_xc[VOL];      // conv0 output (pre-BN)
__device__ float g_q[VOL];       // [t][c][n]
__device__ float g_k[VOL];
__device__ float g_v[VOL];
__device__ float g_s[VOL];       // x + attn_out (pre-BN1)
__device__ float g_part[2 * 64 * 72];
__device__ float g_part2[2 * 64 * 3072];   // conv0-fused BN0 partials
__device__ float g_bn0[128];     // a[64], shift[64]
__device__ float g_bn1[128];
__device__ float g_m[2048];      // [b][c][t]
__device__ float g_w5[800];      // [b][t][25]

__device__ __forceinline__ float leaky(float v) { return v >= 0.f ? v : 0.01f * v; }

// ---------------------------------------------------------------------------
// K1: conv0 (3x3, pad 1, 64->64) -> g_xc  — DIAGONAL-PAIR FFMA2.
// Block: one (b,t,x) row. 256 thr = 32 co-pairs x 8 y-groups of 12 (6 pairs).
// Input rows dual-copied (se aligned, so shifted-by-1) so all three tap
// parities are direct LDS.64 broadcasts. Weight pairs natural LDS.64 from a
// transposed 9x64 tile; diagonal swap applied to the weight pair (pk).
// accA = (co0@y0, co1@y1), accB = (co1@y0, co0@y1); unscrambled in epilogue.
// Epilogue also emits per-(block,channel) sum/sumsq partials for BN0 stats,
// eliminating the separate full-tensor k_stats(0) pass.
// ---------------------------------------------------------------------------
__global__ __launch_bounds__(256) void k_conv0(const float* __restrict__ h,
                                               const float* __restrict__ w,
                                               const float* __restrict__ bias) {
    __shared__ __align__(16) float se[3][104];   // se[r][j] = in(j-1)
    __shared__ __align__(16) float so[3][104];   // so[r][j] = in(j)
    __shared__ __align__(16) float wt[9][64];    // wt[k][o] for current ci
    __shared__ float ss0[256], sq0[256], ss1[256], sq1[256];

    int bt = blockIdx.y;
    int b = bt >> 3, t = bt & 7;
    int x = blockIdx.x;
    int cp = threadIdx.x & 31;        // co-pair index (co = 2cp, 2cp+1)
    int yg = threadIdx.x >> 5;        // 0..7, 12 y's (6 pairs) each
    int ybase = yg * 12;

    u64 accA[6], accB[6];
#pragma unroll
    for (int u = 0; u < 6; u++) { accA[u] = 0ULL; accB[u] = 0ULL; }

    const float* hp = h + ((long)(b * 64) * 8 + t) * 9216;  // + ci*73728

    for (int ci = 0; ci < 64; ci++) {
        __syncthreads();
        for (int i = threadIdx.x; i < 294; i += 256) {
            int r = i / 98, yy = i - r * 98;
            int gx = x + r - 1, gy = yy - 1;
            float v = 0.f;
            if ((unsigned)gx < 96u && (unsigned)gy < 96u)
                v = hp[ci * 73728 + gx * 96 + gy];
            se[r][yy] = v;
            if (yy) so[r][yy - 1] = v;
        }
        for (int i = threadIdx.x; i < 576; i += 256) {
            int o = i / 9, k = i - o * 9;
            wt[k][o] = w[(o * 64 + ci) * 9 + k];
        }
        __syncthreads();

        u64 wN[9], wS[9];
#pragma unroll
        for (int k = 0; k < 9; k++) {
            float2 wv = *(const float2*)&wt[k][2 * cp];
            wN[k] = pk(wv.x, wv.y);
            wS[k] = pk(wv.y, wv.x);
        }

#pragma unroll
        for (int r = 0; r < 3; r++) {
            const u64* pe = (const u64*)&se[r][ybase];   // pe[u]: pair @ ybase+2u
            const u64* po = (const u64*)&so[r][ybase];
#pragma unroll
            for (int u = 0; u < 6; u++) {
                u64 x0 = pe[u];        // tap k=0: (in(y0-1), in(y1-1))
                u64 x1 = po[u];        // tap k=1: (in(y0),   in(y1))
                u64 x2 = pe[u + 1];    // tap k=2: (in(y0+1), in(y1+1))
                accA[u] = fma2(wN[r * 3 + 0], x0, accA[u]);
                accB[u] = fma2(wS[r * 3 + 0], x0, accB[u]);
                accA[u] = fma2(wN[r * 3 + 1], x1, accA[u]);
                accB[u] = fma2(wS[r * 3 + 1], x1, accB[u]);
                accA[u] = fma2(wN[r * 3 + 2], x2, accA[u]);
                accB[u] = fma2(wS[r * 3 + 2], x2, accB[u]);
            }
        }
    }

    // Epilogue: unscramble, add bias, store, and accumulate BN0 partials.
    float bb0 = bias[2 * cp], bb1 = bias[2 * cp + 1];
    float s0 = 0.f, q0 = 0.f, s1 = 0.f, q1 = 0.f;
    float* op0 = g_xc + ((b * 64 + 2 * cp) * 8 + t) * 9216 + x * 96 + ybase;
    float* op1 = op0 + 8 * 9216;
#pragma unroll
    for (int u = 0; u < 6; u++) {
        float2 A = upk(accA[u]);   // (co0@y0, co1@y1)
        float2 B = upk(accB[u]);   // (co1@y0, co0@y1)
        float v00 = A.x + bb0, v01 = B.y + bb0;   // row co0: y0, y1
        float v10 = B.x + bb1, v11 = A.y + bb1;   // row co1: y0, y1
        float2 e0; e0.x = v00; e0.y = v01;
        float2 e1; e1.x = v10; e1.y = v11;
        *(float2*)&op0[2 * u] = e0;
        *(float2*)&op1[2 * u] = e1;
        s0 += v00 + v01; q0 += v00 * v00 + v01 * v01;
        s1 += v10 + v11; q1 += v10 * v10 + v11 * v11;
    }
    __syncthreads();
    ss0[threadIdx.x] = s0; sq0[threadIdx.x] = q0;
    ss1[threadIdx.x] = s1; sq1[threadIdx.x] = q1;
    __syncthreads();
    if (threadIdx.x < 64) {
        int co = threadIdx.x;
        int cpp = co >> 1, sel = co & 1;
        float s = 0.f, q = 0.f;
#pragma unroll
        for (int g = 0; g < 8; g++) {
            int idx = g * 32 + cpp;
            s += sel ? ss1[idx] : ss0[idx];
            q += sel ? sq1[idx] : sq0[idx];
        }
        int bid = blockIdx.y * 96 + blockIdx.x;   // 0..3071
        g_part2[co * 3072 + bid] = s;
        g_part2[196608 + co * 3072 + bid] = q;
    }
}

// ---------------------------------------------------------------------------
// K1b: finalize BN0 from conv0-fused partials (replaces k_stats(0)+finalize)
// ---------------------------------------------------------------------------
__global__ __launch_bounds__(256) void k_bnstat0(const float* __restrict__ gamma,
                                                 const float* __restrict__ beta) {
    int c = blockIdx.x;
    float s = 0.f, q = 0.f;
    for (int i = threadIdx.x; i < 3072; i += 256) {
        s += g_part2[c * 3072 + i];
        q += g_part2[196608 + c * 3072 + i];
    }
    __shared__ float rs[256], rq[256];
    rs[threadIdx.x] = s; rq[threadIdx.x] = q;
    __syncthreads();
    for (int st = 128; st > 0; st >>= 1) {
        if (threadIdx.x < st) { rs[threadIdx.x] += rs[threadIdx.x + st];
                                rq[threadIdx.x] += rq[threadIdx.x + st]; }
        __syncthreads();
    }
    if (threadIdx.x == 0) {
        float mean = rs[0] * (1.f / 294912.f);
        float var = rq[0] * (1.f / 294912.f) - mean * mean;
        float a = gamma[c] * rsqrtf(var + 1e-5f);
        g_bn0[c] = a;
        g_bn0[64 + c] = beta[c] - mean * a;
    }
}

// ---------------------------------------------------------------------------
// K2: per-channel sum / sumsq partials (used for BN1 over g_s)
// ---------------------------------------------------------------------------
__global__ __launch_bounds__(256) void k_stats(int which) {
    const float* src = which ? g_s : g_xc;
    int c = blockIdx.x;
    int chunk = blockIdx.y;
    float s = 0.f, q = 0.f;
    for (int i = threadIdx.x; i < 4096; i += 256) {
        int j = chunk * 4096 + i;
        int b = j / 73728;
        int r = j - b * 73728;
        float v = src[(b * 64 + c) * 73728 + r];
        s += v; q += v * v;
    }
    __shared__ float rs[256], rq[256];
    rs[threadIdx.x] = s; rq[threadIdx.x] = q;
    __syncthreads();
    for (int st = 128; st > 0; st >>= 1) {
        if (threadIdx.x < st) { rs[threadIdx.x] += rs[threadIdx.x + st];
                                rq[threadIdx.x] += rq[threadIdx.x + st]; }
        __syncthreads();
    }
    if (threadIdx.x == 0) {
        g_part[c * 72 + chunk] = rs[0];
        g_part[4608 + c * 72 + chunk] = rq[0];
    }
}

__global__ void k_finalize(int which, const float* __restrict__ gamma,
                           const float* __restrict__ beta) {
    int c = threadIdx.x;  // 64 threads
    float s = 0.f, q = 0.f;
    for (int i = 0; i < 72; i++) { s += g_part[c * 72 + i]; q += g_part[4608 + c * 72 + i]; }
    float mean = s * (1.f / 294912.f);
    float var = q * (1.f / 294912.f) - mean * mean;
    float a = gamma[c] * rsqrtf(var + 1e-5f);
    float* dst = which ? g_bn1 : g_bn0;
    dst[c] = a;
    dst[64 + c] = beta[c] - mean * a;
}

// ---------------------------------------------------------------------------
// K3: QKV projection, diagonal-pair FFMA2 (R15 form, unchanged)
// ---------------------------------------------------------------------------
__global__ __launch_bounds__(256) void k_qkv(const float* __restrict__ W,
                                             const float* __restrict__ Wb) {
    extern __shared__ __align__(16) float sm[];
    float* x_s = sm;                  // 64 * 128 floats = 32KB
    float* w_s = sm + 8192;           // 64 * 196 floats (transposed, padded)
    int bt = blockIdx.y;
    int b = bt >> 3, t = bt & 7;
    int s0 = blockIdx.x * 128;

    for (int i = threadIdx.x; i < 12288; i += 256) {
        int o = i >> 6, c = i & 63;
        w_s[c * 196 + o] = W[i];
    }
    for (int i = threadIdx.x; i < 2048; i += 256) {
        int c = i >> 5, g = (i & 31) * 4;
        float4 v4 = *(const float4*)&g_xc[((b * 64 + c) * 8 + t) * 9216 + s0 + g];
        float a = g_bn0[c], sh = g_bn0[64 + c];
        float4 r4;
        r4.x = leaky(a * v4.x + sh);
        r4.y = leaky(a * v4.y + sh);
        r4.z = leaky(a * v4.z + sh);
        r4.w = leaky(a * v4.w + sh);
        *(float4*)&x_s[c * 128 + g] = r4;
    }
    __syncthreads();

    int pg = threadIdx.x & 31;
    int og = threadIdx.x >> 5;

    for (int p = 0; p < 3; p++) {
        u64 accA[4][2], accB[4][2];
#pragma unroll
        for (int i = 0; i < 4; i++)
#pragma unroll
            for (int j = 0; j < 2; j++) { accA[i][j] = 0ULL; accB[i][j] = 0ULL; }

        for (int c = 0; c < 64; c++) {
            float2 xa = *(const float2*)&x_s[c * 128 + 2 * pg];
            float2 xb = *(const float2*)&x_s[c * 128 + 2 * pg + 64];
            u64 xaN = pk(xa.x, xa.y), xaS = pk(xa.y, xa.x);
            u64 xbN = pk(xb.x, xb.y), xbS = pk(xb.y, xb.x);
            const u64* wp = (const u64*)&w_s[c * 196 + p * 64 + og * 8];
            u64 w0 = wp[0], w1 = wp[1], w2 = wp[2], w3 = wp[3];
            accA[0][0] = fma2(w0, xaN, accA[0][0]);
            accB[0][0] = fma2(w0, xaS, accB[0][0]);
            accA[0][1] = fma2(w0, xbN, accA[0][1]);
            accB[0][1] = fma2(w0, xbS, accB[0][1]);
            accA[1][0] = fma2(w1, xaN, accA[1][0]);
            accB[1][0] = fma2(w1, xaS, accB[1][0]);
            accA[1][1] = fma2(w1, xbN, accA[1][1]);
            accB[1][1] = fma2(w1, xbS, accB[1][1]);
            accA[2][0] = fma2(w2, xaN, accA[2][0]);
            accB[2][0] = fma2(w2, xaS, accB[2][0]);
            accA[2][1] = fma2(w2, xbN, accA[2][1]);
            accB[2][1] = fma2(w2, xbS, accB[2][1]);
            accA[3][0] = fma2(w3, xaN, accA[3][0]);
            accB[3][0] = fma2(w3, xaS, accB[3][0]);
            accA[3][1] = fma2(w3, xbN, accA[3][1]);
            accB[3][1] = fma2(w3, xbS, accB[3][1]);
        }

        float* dst = (p == 0) ? g_q : (p == 1 ? g_k : g_v);
        float scale = (p == 0) ? 0.35355339059327373f : 1.f;
#pragma unroll
        for (int i = 0; i < 4; i++) {
            int o0 = og * 8 + 2 * i;
            float b0 = Wb[p * 64 + o0], b1 = Wb[p * 64 + o0 + 1];
            long r0 = (long)(t * 64 + o0) * 36864 + b * 9216 + s0 + 2 * pg;
            long r1 = r0 + 36864;
#pragma unroll
            for (int j = 0; j < 2; j++) {
                float2 A = upk(accA[i][j]);
                float2 Bv = upk(accB[i][j]);
                float2 e0, e1;
                e0.x = (A.x + b0) * scale;  e0.y = (Bv.x + b0) * scale;
                e1.x = (Bv.y + b1) * scale; e1.y = (A.y + b1) * scale;
                *(float2*)&dst[r0 + 64 * j] = e0;
                *(float2*)&dst[r1 + 64 * j] = e1;
            }
        }
    }
}

// ---------------------------------------------------------------------------
// K4: attention core + out-proj + residual -> g_s    [R8 form]
// ---------------------------------------------------------------------------
__global__ __launch_bounds__(256) void k_attn(const float* __restrict__ Wo,
                                              const float* __restrict__ bo) {
    extern __shared__ __align__(16) float sm[];
    float* q_s  = sm;              // 512*17 = 8704
    float* k_s  = sm + 8704;
    float* v_s  = sm + 17408;
    float* o_s  = sm + 26112;      // 16*516 = 8256
    float* wo_s = sm + 34368;      // 4096
    float* ab_s = sm + 38464;      // 128
    float* bo_s = sm + 38592;      // 64

    int n0 = blockIdx.x * 16;
    int b = n0 / 9216;
    int s0 = n0 - b * 9216;

    for (int i = threadIdx.x; i < 8192; i += 256) {
        int tc = i >> 4, nl = i & 15;
        int ga = tc * 36864 + n0 + nl;
        q_s[tc * 17 + nl] = g_q[ga];
        k_s[tc * 17 + nl] = g_k[ga];
        v_s[tc * 17 + nl] = g_v[ga];
    }
    for (int i = threadIdx.x; i < 4096; i += 256) wo_s[i] = Wo[i];
    if (threadIdx.x < 128) ab_s[threadIdx.x] = g_bn0[threadIdx.x];
    else if (threadIdx.x < 192) bo_s[threadIdx.x - 128] = bo[threadIdx.x - 128];
    __syncthreads();

    // Phase B: per-(token, head) attention over T=8
    {
        int u = threadIdx.x >> 7;
        int rem = threadIdx.x & 127;
        int nl = rem & 15;
        int hh = rem >> 4;
#pragma unroll
        for (int qi = 0; qi < 4; qi++) {
            int qt = u * 4 + qi;
            float qr[8];
#pragma unroll
            for (int d = 0; d < 8; d++) qr[d] = q_s[(qt * 64 + hh * 8 + d) * 17 + nl];
            float sc[8];
#pragma unroll
            for (int kt = 0; kt < 8; kt++) {
                float s = 0.f;
#pragma unroll
                for (int d = 0; d < 8; d++)
                    s = fmaf(qr[d], k_s[(kt * 64 + hh * 8 + d) * 17 + nl], s);
                sc[kt] = s;
            }
            float mx = sc[0];
#pragma unroll
            for (int kt = 1; kt < 8; kt++) mx = fmaxf(mx, sc[kt]);
            float sum = 0.f;
#pragma unroll
            for (int kt = 0; kt < 8; kt++) { sc[kt] = __expf(sc[kt] - mx); sum += sc[kt]; }
            float inv = 1.f / sum;
#pragma unroll
            for (int d = 0; d < 8; d++) {
                float o = 0.f;
#pragma unroll
                for (int kt = 0; kt < 8; kt++)
                    o = fmaf(sc[kt], v_s[(kt * 64 + hh * 8 + d) * 17 + nl], o);
                o_s[nl * 516 + qt * 64 + hh * 8 + d] = o * inv;
            }
        }
    }
    __syncthreads();

    // Phase C: out-proj + residual (x = leaky(bn0(xc))) -> g_s
    for (int idx = threadIdx.x; idx < 8192; idx += 256) {
        int nl = idx & 15;
        int co = (idx >> 4) & 63;
        int t = idx >> 10;
        float acc = bo_s[co];
        const float* orow = &o_s[nl * 516 + t * 64];
        const float* wrow = &wo_s[co * 64];
#pragma unroll
        for (int c = 0; c < 64; c += 4) {
            float4 ov = *(const float4*)&orow[c];
            float4 wv = *(const float4*)&wrow[c];
            acc = fmaf(ov.x, wv.x, acc);
            acc = fmaf(ov.y, wv.y, acc);
            acc = fmaf(ov.z, wv.z, acc);
            acc = fmaf(ov.w, wv.w, acc);
        }
        int ga = ((b * 64 + co) * 8 + t) * 9216 + s0 + nl;
        float x = leaky(ab_s[co] * g_xc[ga] + ab_s[64 + co]);
        g_s[ga] = x + acc;
    }
}

// ---------------------------------------------------------------------------
// K6: m[b,c,t] = spatial mean of leaky(bn1(g_s))
// ---------------------------------------------------------------------------
__global__ __launch_bounds__(256) void k_mred() {
    int bct = blockIdx.x;
    int c = (bct >> 3) & 63;
    float a = g_bn1[c], sh = g_bn1[64 + c];
    const float* p = g_s + bct * 9216;
    float s = 0.f;
    for (int i = threadIdx.x; i < 9216; i += 256) s += leaky(a * p[i] + sh);
    __shared__ float rs[256];
    rs[threadIdx.x] = s;
    __syncthreads();
    for (int st = 128; st > 0; st >>= 1) {
        if (threadIdx.x < st) rs[threadIdx.x] += rs[threadIdx.x + st];
        __syncthreads();
    }
    if (threadIdx.x == 0) g_m[bct] = rs[0] * (1.f / 9216.f);
}

// ---------------------------------------------------------------------------
// K7: per-(b,t) 5x5 kernels
// ---------------------------------------------------------------------------
__global__ void k_kern(const float* __restrict__ w1, const float* __restrict__ b1) {
    for (int i = threadIdx.x; i < 800; i += 256) {
        int b = i / 200;
        int rem = i - b * 200;
        int o = rem / 8;
        int t = rem - o * 8;
        float s = b1[o];
        for (int c = 0; c < 64; c++)
            s = fmaf(w1[o * 64 + c], g_m[(b * 64 + c) * 8 + t], s);
        g_w5[(b * 8 + t) * 25 + o] = s;
    }
}

// ---------------------------------------------------------------------------
// K8: dynamic depthwise 5x5 conv -> d_out      [R8 scalar form]
// ---------------------------------------------------------------------------
__global__ __launch_bounds__(256) void k_dyn(const float* __restrict__ h,
                                             float* __restrict__ out) {
    __shared__ __align__(16) float in_s[12][100];
    __shared__ float w_s[25];
    int plane = blockIdx.y;          // (b*64+c)*8+t
    int b = plane >> 9;
    int t = plane & 7;
    int bt = b * 8 + t;
    int x0 = blockIdx.x * 8;

    if (threadIdx.x < 25) w_s[threadIdx.x] = g_w5[bt * 25 + threadIdx.x];
    for (int i = threadIdx.x; i < 1200; i += 256) {
        int r = i / 100, cc = i - r * 100;
        int gx = x0 + r - 2, gy = cc - 2;
        float v = 0.f;
        if ((unsigned)gx < 96u && (unsigned)gy < 96u)
            v = h[plane * 9216 + gx * 96 + gy];
        in_s[r][cc] = v;
    }
    __syncthreads();
    for (int o = threadIdx.x; o < 768; o += 256) {
        int xr = o / 96, y = o - xr * 96;
        float acc = 0.f;
#pragma unroll
        for (int di = 0; di < 5; di++)
#pragma unroll
            for (int dj = 0; dj < 5; dj++)
                acc = fmaf(in_s[xr + di][y + dj], w_s[di * 5 + dj], acc);
        out[plane * 9216 + (x0 + xr) * 96 + y] = acc;
    }
}

// ---------------------------------------------------------------------------
extern "C" void kernel_launch(void* const* d_in, const int* in_sizes, int n_in,
                              void* d_out, int out_size) {
    const float* h       = (const float*)d_in[0];
    const float* conv0_w = (const float*)d_in[1];
    const float* conv0_b = (const float*)d_in[2];
    const float* bn0_g   = (const float*)d_in[3];
    const float* bn0_b   = (const float*)d_in[4];
    const float* bn1_g   = (const float*)d_in[5];
    const float* bn1_b   = (const float*)d_in[6];
    const float* in_w    = (const float*)d_in[7];
    const float* in_b    = (const float*)d_in[8];
    const float* out_w   = (const float*)d_in[9];
    const float* out_b   = (const float*)d_in[10];
    const float* c1_w    = (const float*)d_in[11];
    const float* c1_b    = (const float*)d_in[12];
    float* out = (float*)d_out;

    cudaFuncSetAttribute(k_qkv,  cudaFuncAttributeMaxDynamicSharedMemorySize, 82944);
    cudaFuncSetAttribute(k_attn, cudaFuncAttributeMaxDynamicSharedMemorySize, 156 * 1024);

    k_conv0<<<dim3(96, 32), 256>>>(h, conv0_w, conv0_b);
    k_bnstat0<<<64, 256>>>(bn0_g, bn0_b);
    k_qkv<<<dim3(72, 32), 256, 82944>>>(in_w, in_b);
    k_attn<<<2304, 256, 154624>>>(out_w, out_b);
    k_stats<<<dim3(64, 72), 256>>>(1);
    k_finalize<<<1, 64>>>(1, bn1_g, bn1_b);
    k_mred<<<2048, 256>>>();
    k_kern<<<1, 256>>>(c1_w, c1_b);
    k_dyn<<<dim3(12, 2048), 256>>>(h, out);
}

// round 17
// speedup vs baseline: 1.2715x; 1.0409x over previous
#include <cuda_runtime.h>
#include <math.h>

typedef unsigned long long u64;

// Packed fp32x2 helpers (SASS FFMA2 path — only reachable via PTX)
__device__ __forceinline__ u64 pk(float lo, float hi) {
    u64 r; asm("mov.b64 %0, {%1, %2};" : "=l"(r) : "f"(lo), "f"(hi)); return r;
}
__device__ __forceinline__ float2 upk(u64 v) {
    float2 r; asm("mov.b64 {%0, %1}, %2;" : "=f"(r.x), "=f"(r.y) : "l"(v)); return r;
}
__device__ __forceinline__ u64 fma2(u64 a, u64 b, u64 c) {
    u64 d; asm("fma.rn.f32x2 %0, %1, %2, %3;" : "=l"(d) : "l"(a), "l"(b), "l"(c)); return d;
}

// Problem dims
#define VOL 18874368       // 4*64*8*96*96

// Scratch (device globals: the sanctioned no-alloc workaround)
__device__ float g_xc[VOL];      // conv0 output (pre-BN)
__device__ float g_q[VOL];       // [t][c][n]
__device__ float g_k[VOL];
__device__ float g_v[VOL];
__device__ float g_s[VOL];       // x + attn_out (pre-BN1)
__device__ float g_part[2 * 64 * 72];
__device__ float g_part2[2 * 64 * 3072];   // conv0-fused BN0 partials
__device__ float g_bn0[128];     // a[64], shift[64]
__device__ float g_bn1[128];
__device__ float g_m[2048];      // [b][c][t]
__device__ float g_w5[800];      // [b][t][25]

__device__ __forceinline__ float leaky(float v) { return v >= 0.f ? v : 0.01f * v; }

// ---------------------------------------------------------------------------
// K1: conv0 (3x3, pad 1, 64->64) -> g_xc  — DIAGONAL-PAIR FFMA2 (R16 form)
// + fused BN0 partials.
// ---------------------------------------------------------------------------
__global__ __launch_bounds__(256) void k_conv0(const float* __restrict__ h,
                                               const float* __restrict__ w,
                                               const float* __restrict__ bias) {
    __shared__ __align__(16) float se[3][104];   // se[r][j] = in(j-1)
    __shared__ __align__(16) float so[3][104];   // so[r][j] = in(j)
    __shared__ __align__(16) float wt[9][64];    // wt[k][o] for current ci
    __shared__ float ss0[256], sq0[256], ss1[256], sq1[256];

    int bt = blockIdx.y;
    int b = bt >> 3, t = bt & 7;
    int x = blockIdx.x;
    int cp = threadIdx.x & 31;        // co-pair index (co = 2cp, 2cp+1)
    int yg = threadIdx.x >> 5;        // 0..7, 12 y's (6 pairs) each
    int ybase = yg * 12;

    u64 accA[6], accB[6];
#pragma unroll
    for (int u = 0; u < 6; u++) { accA[u] = 0ULL; accB[u] = 0ULL; }

    const float* hp = h + ((long)(b * 64) * 8 + t) * 9216;  // + ci*73728

    for (int ci = 0; ci < 64; ci++) {
        __syncthreads();
        for (int i = threadIdx.x; i < 294; i += 256) {
            int r = i / 98, yy = i - r * 98;
            int gx = x + r - 1, gy = yy - 1;
            float v = 0.f;
            if ((unsigned)gx < 96u && (unsigned)gy < 96u)
                v = hp[ci * 73728 + gx * 96 + gy];
            se[r][yy] = v;
            if (yy) so[r][yy - 1] = v;
        }
        for (int i = threadIdx.x; i < 576; i += 256) {
            int o = i / 9, k = i - o * 9;
            wt[k][o] = w[(o * 64 + ci) * 9 + k];
        }
        __syncthreads();

        u64 wN[9], wS[9];
#pragma unroll
        for (int k = 0; k < 9; k++) {
            float2 wv = *(const float2*)&wt[k][2 * cp];
            wN[k] = pk(wv.x, wv.y);
            wS[k] = pk(wv.y, wv.x);
        }

#pragma unroll
        for (int r = 0; r < 3; r++) {
            const u64* pe = (const u64*)&se[r][ybase];
            const u64* po = (const u64*)&so[r][ybase];
#pragma unroll
            for (int u = 0; u < 6; u++) {
                u64 x0 = pe[u];
                u64 x1 = po[u];
                u64 x2 = pe[u + 1];
                accA[u] = fma2(wN[r * 3 + 0], x0, accA[u]);
                accB[u] = fma2(wS[r * 3 + 0], x0, accB[u]);
                accA[u] = fma2(wN[r * 3 + 1], x1, accA[u]);
                accB[u] = fma2(wS[r * 3 + 1], x1, accB[u]);
                accA[u] = fma2(wN[r * 3 + 2], x2, accA[u]);
                accB[u] = fma2(wS[r * 3 + 2], x2, accB[u]);
            }
        }
    }

    float bb0 = bias[2 * cp], bb1 = bias[2 * cp + 1];
    float s0 = 0.f, q0 = 0.f, s1 = 0.f, q1 = 0.f;
    float* op0 = g_xc + ((b * 64 + 2 * cp) * 8 + t) * 9216 + x * 96 + ybase;
    float* op1 = op0 + 8 * 9216;
#pragma unroll
    for (int u = 0; u < 6; u++) {
        float2 A = upk(accA[u]);
        float2 B = upk(accB[u]);
        float v00 = A.x + bb0, v01 = B.y + bb0;
        float v10 = B.x + bb1, v11 = A.y + bb1;
        float2 e0; e0.x = v00; e0.y = v01;
        float2 e1; e1.x = v10; e1.y = v11;
        *(float2*)&op0[2 * u] = e0;
        *(float2*)&op1[2 * u] = e1;
        s0 += v00 + v01; q0 += v00 * v00 + v01 * v01;
        s1 += v10 + v11; q1 += v10 * v10 + v11 * v11;
    }
    __syncthreads();
    ss0[threadIdx.x] = s0; sq0[threadIdx.x] = q0;
    ss1[threadIdx.x] = s1; sq1[threadIdx.x] = q1;
    __syncthreads();
    if (threadIdx.x < 64) {
        int co = threadIdx.x;
        int cpp = co >> 1, sel = co & 1;
        float s = 0.f, q = 0.f;
#pragma unroll
        for (int g = 0; g < 8; g++) {
            int idx = g * 32 + cpp;
            s += sel ? ss1[idx] : ss0[idx];
            q += sel ? sq1[idx] : sq0[idx];
        }
        int bid = blockIdx.y * 96 + blockIdx.x;
        g_part2[co * 3072 + bid] = s;
        g_part2[196608 + co * 3072 + bid] = q;
    }
}

// ---------------------------------------------------------------------------
// K1b: finalize BN0 from conv0-fused partials
// ---------------------------------------------------------------------------
__global__ __launch_bounds__(256) void k_bnstat0(const float* __restrict__ gamma,
                                                 const float* __restrict__ beta) {
    int c = blockIdx.x;
    float s = 0.f, q = 0.f;
    for (int i = threadIdx.x; i < 3072; i += 256) {
        s += g_part2[c * 3072 + i];
        q += g_part2[196608 + c * 3072 + i];
    }
    __shared__ float rs[256], rq[256];
    rs[threadIdx.x] = s; rq[threadIdx.x] = q;
    __syncthreads();
    for (int st = 128; st > 0; st >>= 1) {
        if (threadIdx.x < st) { rs[threadIdx.x] += rs[threadIdx.x + st];
                                rq[threadIdx.x] += rq[threadIdx.x + st]; }
        __syncthreads();
    }
    if (threadIdx.x == 0) {
        float mean = rs[0] * (1.f / 294912.f);
        float var = rq[0] * (1.f / 294912.f) - mean * mean;
        float a = gamma[c] * rsqrtf(var + 1e-5f);
        g_bn0[c] = a;
        g_bn0[64 + c] = beta[c] - mean * a;
    }
}

// ---------------------------------------------------------------------------
// K2: per-channel sum / sumsq partials (used for BN1 over g_s)
// ---------------------------------------------------------------------------
__global__ __launch_bounds__(256) void k_stats(int which) {
    const float* src = which ? g_s : g_xc;
    int c = blockIdx.x;
    int chunk = blockIdx.y;
    float s = 0.f, q = 0.f;
    for (int i = threadIdx.x; i < 4096; i += 256) {
        int j = chunk * 4096 + i;
        int b = j / 73728;
        int r = j - b * 73728;
        float v = src[(b * 64 + c) * 73728 + r];
        s += v; q += v * v;
    }
    __shared__ float rs[256], rq[256];
    rs[threadIdx.x] = s; rq[threadIdx.x] = q;
    __syncthreads();
    for (int st = 128; st > 0; st >>= 1) {
        if (threadIdx.x < st) { rs[threadIdx.x] += rs[threadIdx.x + st];
                                rq[threadIdx.x] += rq[threadIdx.x + st]; }
        __syncthreads();
    }
    if (threadIdx.x == 0) {
        g_part[c * 72 + chunk] = rs[0];
        g_part[4608 + c * 72 + chunk] = rq[0];
    }
}

__global__ void k_finalize(int which, const float* __restrict__ gamma,
                           const float* __restrict__ beta) {
    int c = threadIdx.x;  // 64 threads
    float s = 0.f, q = 0.f;
    for (int i = 0; i < 72; i++) { s += g_part[c * 72 + i]; q += g_part[4608 + c * 72 + i]; }
    float mean = s * (1.f / 294912.f);
    float var = q * (1.f / 294912.f) - mean * mean;
    float a = gamma[c] * rsqrtf(var + 1e-5f);
    float* dst = which ? g_bn1 : g_bn0;
    dst[c] = a;
    dst[64 + c] = beta[c] - mean * a;
}

// ---------------------------------------------------------------------------
// K3: QKV projection, diagonal-pair FFMA2 (R15 form, unchanged)
// ---------------------------------------------------------------------------
__global__ __launch_bounds__(256) void k_qkv(const float* __restrict__ W,
                                             const float* __restrict__ Wb) {
    extern __shared__ __align__(16) float sm[];
    float* x_s = sm;                  // 64 * 128 floats = 32KB
    float* w_s = sm + 8192;           // 64 * 196 floats (transposed, padded)
    int bt = blockIdx.y;
    int b = bt >> 3, t = bt & 7;
    int s0 = blockIdx.x * 128;

    for (int i = threadIdx.x; i < 12288; i += 256) {
        int o = i >> 6, c = i & 63;
        w_s[c * 196 + o] = W[i];
    }
    for (int i = threadIdx.x; i < 2048; i += 256) {
        int c = i >> 5, g = (i & 31) * 4;
        float4 v4 = *(const float4*)&g_xc[((b * 64 + c) * 8 + t) * 9216 + s0 + g];
        float a = g_bn0[c], sh = g_bn0[64 + c];
        float4 r4;
        r4.x = leaky(a * v4.x + sh);
        r4.y = leaky(a * v4.y + sh);
        r4.z = leaky(a * v4.z + sh);
        r4.w = leaky(a * v4.w + sh);
        *(float4*)&x_s[c * 128 + g] = r4;
    }
    __syncthreads();

    int pg = threadIdx.x & 31;
    int og = threadIdx.x >> 5;

    for (int p = 0; p < 3; p++) {
        u64 accA[4][2], accB[4][2];
#pragma unroll
        for (int i = 0; i < 4; i++)
#pragma unroll
            for (int j = 0; j < 2; j++) { accA[i][j] = 0ULL; accB[i][j] = 0ULL; }

        for (int c = 0; c < 64; c++) {
            float2 xa = *(const float2*)&x_s[c * 128 + 2 * pg];
            float2 xb = *(const float2*)&x_s[c * 128 + 2 * pg + 64];
            u64 xaN = pk(xa.x, xa.y), xaS = pk(xa.y, xa.x);
            u64 xbN = pk(xb.x, xb.y), xbS = pk(xb.y, xb.x);
            const u64* wp = (const u64*)&w_s[c * 196 + p * 64 + og * 8];
            u64 w0 = wp[0], w1 = wp[1], w2 = wp[2], w3 = wp[3];
            accA[0][0] = fma2(w0, xaN, accA[0][0]);
            accB[0][0] = fma2(w0, xaS, accB[0][0]);
            accA[0][1] = fma2(w0, xbN, accA[0][1]);
            accB[0][1] = fma2(w0, xbS, accB[0][1]);
            accA[1][0] = fma2(w1, xaN, accA[1][0]);
            accB[1][0] = fma2(w1, xaS, accB[1][0]);
            accA[1][1] = fma2(w1, xbN, accA[1][1]);
            accB[1][1] = fma2(w1, xbS, accB[1][1]);
            accA[2][0] = fma2(w2, xaN, accA[2][0]);
            accB[2][0] = fma2(w2, xaS, accB[2][0]);
            accA[2][1] = fma2(w2, xbN, accA[2][1]);
            accB[2][1] = fma2(w2, xbS, accB[2][1]);
            accA[3][0] = fma2(w3, xaN, accA[3][0]);
            accB[3][0] = fma2(w3, xaS, accB[3][0]);
            accA[3][1] = fma2(w3, xbN, accA[3][1]);
            accB[3][1] = fma2(w3, xbS, accB[3][1]);
        }

        float* dst = (p == 0) ? g_q : (p == 1 ? g_k : g_v);
        float scale = (p == 0) ? 0.35355339059327373f : 1.f;
#pragma unroll
        for (int i = 0; i < 4; i++) {
            int o0 = og * 8 + 2 * i;
            float b0 = Wb[p * 64 + o0], b1 = Wb[p * 64 + o0 + 1];
            long r0 = (long)(t * 64 + o0) * 36864 + b * 9216 + s0 + 2 * pg;
            long r1 = r0 + 36864;
#pragma unroll
            for (int j = 0; j < 2; j++) {
                float2 A = upk(accA[i][j]);
                float2 Bv = upk(accB[i][j]);
                float2 e0, e1;
                e0.x = (A.x + b0) * scale;  e0.y = (Bv.x + b0) * scale;
                e1.x = (Bv.y + b1) * scale; e1.y = (A.y + b1) * scale;
                *(float2*)&dst[r0 + 64 * j] = e0;
                *(float2*)&dst[r1 + 64 * j] = e1;
            }
        }
    }
}

// ---------------------------------------------------------------------------
// K4: attention core + out-proj + residual -> g_s
// TOK=8 tokens/block, pad 9, 86.9KB smem, forced 2 CTA/SM (128 regs).
// Phase B: 8nl x 8hh x 4u, 2 qt each. Phase C: 8t x 64co x 8nl.
// ---------------------------------------------------------------------------
__global__ __launch_bounds__(256, 2) void k_attn(const float* __restrict__ Wo,
                                                 const float* __restrict__ bo) {
    extern __shared__ __align__(16) float sm[];
    float* q_s  = sm;              // 512*9 = 4608
    float* k_s  = sm + 4608;
    float* v_s  = sm + 9216;
    float* o_s  = sm + 13824;      // 8*516 = 4128
    float* wo_s = sm + 17952;      // 4096
    float* ab_s = sm + 22048;      // 128
    float* bo_s = sm + 22176;      // 64   (total 22240 floats = 88960 B)

    int n0 = blockIdx.x * 8;
    int b = n0 / 9216;
    int s0 = n0 - b * 9216;

    for (int i = threadIdx.x; i < 4096; i += 256) {
        int tc = i >> 3, nl = i & 7;
        int ga = tc * 36864 + n0 + nl;
        q_s[tc * 9 + nl] = g_q[ga];
        k_s[tc * 9 + nl] = g_k[ga];
        v_s[tc * 9 + nl] = g_v[ga];
    }
    for (int i = threadIdx.x; i < 1024; i += 256)
        *(float4*)&wo_s[i * 4] = *(const float4*)&Wo[i * 4];
    if (threadIdx.x < 128) ab_s[threadIdx.x] = g_bn0[threadIdx.x];
    else if (threadIdx.x < 192) bo_s[threadIdx.x - 128] = bo[threadIdx.x - 128];
    __syncthreads();

    // Phase B: per-(token, head) attention over T=8
    {
        int u = threadIdx.x >> 6;         // 0..3
        int rem = threadIdx.x & 63;
        int nl = rem & 7;
        int hh = rem >> 3;                // 0..7
#pragma unroll
        for (int qi = 0; qi < 2; qi++) {
            int qt = u * 2 + qi;
            float qr[8];
#pragma unroll
            for (int d = 0; d < 8; d++) qr[d] = q_s[(qt * 64 + hh * 8 + d) * 9 + nl];
            float sc[8];
#pragma unroll
            for (int kt = 0; kt < 8; kt++) {
                float s = 0.f;
#pragma unroll
                for (int d = 0; d < 8; d++)
                    s = fmaf(qr[d], k_s[(kt * 64 + hh * 8 + d) * 9 + nl], s);
                sc[kt] = s;
            }
            float mx = sc[0];
#pragma unroll
            for (int kt = 1; kt < 8; kt++) mx = fmaxf(mx, sc[kt]);
            float sum = 0.f;
#pragma unroll
            for (int kt = 0; kt < 8; kt++) { sc[kt] = __expf(sc[kt] - mx); sum += sc[kt]; }
            float inv = 1.f / sum;
#pragma unroll
            for (int d = 0; d < 8; d++) {
                float o = 0.f;
#pragma unroll
                for (int kt = 0; kt < 8; kt++)
                    o = fmaf(sc[kt], v_s[(kt * 64 + hh * 8 + d) * 9 + nl], o);
                o_s[nl * 516 + qt * 64 + hh * 8 + d] = o * inv;
            }
        }
    }
    __syncthreads();

    // Phase C: out-proj + residual (x = leaky(bn0(xc))) -> g_s
    for (int idx = threadIdx.x; idx < 4096; idx += 256) {
        int nl = idx & 7;
        int co = (idx >> 3) & 63;
        int t = idx >> 9;
        float acc = bo_s[co];
        const float* orow = &o_s[nl * 516 + t * 64];
        const float* wrow = &wo_s[co * 64];
#pragma unroll
        for (int c = 0; c < 64; c += 4) {
            float4 ov = *(const float4*)&orow[c];
            float4 wv = *(const float4*)&wrow[c];
            acc = fmaf(ov.x, wv.x, acc);
            acc = fmaf(ov.y, wv.y, acc);
            acc = fmaf(ov.z, wv.z, acc);
            acc = fmaf(ov.w, wv.w, acc);
        }
        int ga = ((b * 64 + co) * 8 + t) * 9216 + s0 + nl;
        float x = leaky(ab_s[co] * g_xc[ga] + ab_s[64 + co]);
        g_s[ga] = x + acc;
    }
}

// ---------------------------------------------------------------------------
// K6: m[b,c,t] = spatial mean of leaky(bn1(g_s))
// ---------------------------------------------------------------------------
__global__ __launch_bounds__(256) void k_mred() {
    int bct = blockIdx.x;
    int c = (bct >> 3) & 63;
    float a = g_bn1[c], sh = g_bn1[64 + c];
    const float* p = g_s + bct * 9216;
    float s = 0.f;
    for (int i = threadIdx.x; i < 9216; i += 256) s += leaky(a * p[i] + sh);
    __shared__ float rs[256];
    rs[threadIdx.x] = s;
    __syncthreads();
    for (int st = 128; st > 0; st >>= 1) {
        if (threadIdx.x < st) rs[threadIdx.x] += rs[threadIdx.x + st];
        __syncthreads();
    }
    if (threadIdx.x == 0) g_m[bct] = rs[0] * (1.f / 9216.f);
}

// ---------------------------------------------------------------------------
// K7: per-(b,t) 5x5 kernels
// ---------------------------------------------------------------------------
__global__ void k_kern(const float* __restrict__ w1, const float* __restrict__ b1) {
    for (int i = threadIdx.x; i < 800; i += 256) {
        int b = i / 200;
        int rem = i - b * 200;
        int o = rem / 8;
        int t = rem - o * 8;
        float s = b1[o];
        for (int c = 0; c < 64; c++)
            s = fmaf(w1[o * 64 + c], g_m[(b * 64 + c) * 8 + t], s);
        g_w5[(b * 8 + t) * 25 + o] = s;
    }
}

// ---------------------------------------------------------------------------
// K8: dynamic depthwise 5x5 conv -> d_out      [R8 scalar form]
// ---------------------------------------------------------------------------
__global__ __launch_bounds__(256) void k_dyn(const float* __restrict__ h,
                                             float* __restrict__ out) {
    __shared__ __align__(16) float in_s[12][100];
    __shared__ float w_s[25];
    int plane = blockIdx.y;          // (b*64+c)*8+t
    int b = plane >> 9;
    int t = plane & 7;
    int bt = b * 8 + t;
    int x0 = blockIdx.x * 8;

    if (threadIdx.x < 25) w_s[threadIdx.x] = g_w5[bt * 25 + threadIdx.x];
    for (int i = threadIdx.x; i < 1200; i += 256) {
        int r = i / 100, cc = i - r * 100;
        int gx = x0 + r - 2, gy = cc - 2;
        float v = 0.f;
        if ((unsigned)gx < 96u && (unsigned)gy < 96u)
            v = h[plane * 9216 + gx * 96 + gy];
        in_s[r][cc] = v;
    }
    __syncthreads();
    for (int o = threadIdx.x; o < 768; o += 256) {
        int xr = o / 96, y = o - xr * 96;
        float acc = 0.f;
#pragma unroll
        for (int di = 0; di < 5; di++)
#pragma unroll
            for (int dj = 0; dj < 5; dj++)
                acc = fmaf(in_s[xr + di][y + dj], w_s[di * 5 + dj], acc);
        out[plane * 9216 + (x0 + xr) * 96 + y] = acc;
    }
}

// ---------------------------------------------------------------------------
extern "C" void kernel_launch(void* const* d_in, const int* in_sizes, int n_in,
                              void* d_out, int out_size) {
    const float* h       = (const float*)d_in[0];
    const float* conv0_w = (const float*)d_in[1];
    const float* conv0_b = (const float*)d_in[2];
    const float* bn0_g   = (const float*)d_in[3];
    const float* bn0_b   = (const float*)d_in[4];
    const float* bn1_g   = (const float*)d_in[5];
    const float* bn1_b   = (const float*)d_in[6];
    const float* in_w    = (const float*)d_in[7];
    const float* in_b    = (const float*)d_in[8];
    const float* out_w   = (const float*)d_in[9];
    const float* out_b   = (const float*)d_in[10];
    const float* c1_w    = (const float*)d_in[11];
    const float* c1_b    = (const float*)d_in[12];
    float* out = (float*)d_out;

    cudaFuncSetAttribute(k_qkv,  cudaFuncAttributeMaxDynamicSharedMemorySize, 82944);
    cudaFuncSetAttribute(k_attn, cudaFuncAttributeMaxDynamicSharedMemorySize, 88960);

    k_conv0<<<dim3(96, 32), 256>>>(h, conv0_w, conv0_b);
    k_bnstat0<<<64, 256>>>(bn0_g, bn0_b);
    k_qkv<<<dim3(72, 32), 256, 82944>>>(in_w, in_b);
    k_attn<<<4608, 256, 88960>>>(out_w, out_b);
    k_stats<<<dim3(64, 72), 256>>>(1);
    k_finalize<<<1, 64>>>(1, bn1_g, bn1_b);
    k_mred<<<2048, 256>>>();
    k_kern<<<1, 256>>>(c1_w, c1_b);
    k_dyn<<<dim3(12, 2048), 256>>>(h, out);
}